// round 1
// baseline (speedup 1.0000x reference)
#include <cuda_runtime.h>
#include <math.h>

#define D_MODEL 2048
#define DKV     512
#define LSEQ    2048
#define BATCH   2
#define NROWS   (BATCH * LSEQ)   // 4096

// -------- scratch (no allocation allowed; device globals) --------
__device__ float g_Q[(size_t)NROWS * D_MODEL];
__device__ float g_K[(size_t)NROWS * DKV];
__device__ float g_V[(size_t)NROWS * DKV];
__device__ float g_AO[(size_t)NROWS * D_MODEL];

// =================================================================
// GEMM: C[M,N] = A[M,K] @ B[N,K]^T   (both row-major, K contiguous)
// 128x128 tile, BK=16, 256 threads, 8x8 per thread.
// =================================================================
__global__ void __launch_bounds__(256) gemm_nt(const float* __restrict__ A,
                                               const float* __restrict__ B,
                                               float* __restrict__ C,
                                               int M, int N, int K) {
    __shared__ float As[16][128];
    __shared__ float Bs[16][128];
    const int t  = threadIdx.x;
    const int tx = t & 15, ty = t >> 4;
    const float* Ab = A + (size_t)blockIdx.y * 128 * K;
    const float* Bb = B + (size_t)blockIdx.x * 128 * K;

    float acc[8][8];
#pragma unroll
    for (int i = 0; i < 8; i++)
#pragma unroll
        for (int j = 0; j < 8; j++) acc[i][j] = 0.f;

    for (int kt = 0; kt < K; kt += 16) {
#pragma unroll
        for (int e = t; e < 512; e += 256) {
            int row = e >> 2;
            int c4  = (e & 3) << 2;
            float4 va = *(const float4*)(Ab + (size_t)row * K + kt + c4);
            As[c4 + 0][row] = va.x; As[c4 + 1][row] = va.y;
            As[c4 + 2][row] = va.z; As[c4 + 3][row] = va.w;
            float4 vb = *(const float4*)(Bb + (size_t)row * K + kt + c4);
            Bs[c4 + 0][row] = vb.x; Bs[c4 + 1][row] = vb.y;
            Bs[c4 + 2][row] = vb.z; Bs[c4 + 3][row] = vb.w;
        }
        __syncthreads();
#pragma unroll
        for (int k = 0; k < 16; k++) {
            float a[8], b[8];
            *(float4*)(a)     = *(const float4*)&As[k][ty * 8];
            *(float4*)(a + 4) = *(const float4*)&As[k][ty * 8 + 4];
            *(float4*)(b)     = *(const float4*)&Bs[k][tx * 8];
            *(float4*)(b + 4) = *(const float4*)&Bs[k][tx * 8 + 4];
#pragma unroll
            for (int i = 0; i < 8; i++)
#pragma unroll
                for (int j = 0; j < 8; j++)
                    acc[i][j] = fmaf(a[i], b[j], acc[i][j]);
        }
        __syncthreads();
    }
    float* Cb = C + (size_t)(blockIdx.y * 128 + ty * 8) * N + blockIdx.x * 128 + tx * 8;
#pragma unroll
    for (int i = 0; i < 8; i++) {
        *(float4*)(Cb + (size_t)i * N)     = make_float4(acc[i][0], acc[i][1], acc[i][2], acc[i][3]);
        *(float4*)(Cb + (size_t)i * N + 4) = make_float4(acc[i][4], acc[i][5], acc[i][6], acc[i][7]);
    }
}

// =================================================================
// RoPE (in place). X is [NROWS, nheads*64]; position = row % LSEQ.
// One thread per (row, head, j<32) pair handles elems j and j+32.
// =================================================================
__global__ void rope_kernel(float* __restrict__ X, int nheads, int total) {
    int idx = blockIdx.x * blockDim.x + threadIdx.x;
    if (idx >= total) return;
    int j   = idx & 31;
    int h   = (idx >> 5) % nheads;
    int row = idx / (nheads * 32);
    int l   = row & (LSEQ - 1);
    float inv = 1.0f / powf(10000.0f, (float)j * (1.0f / 32.0f));
    float ang = (float)l * inv;
    float s, c;
    sincosf(ang, &s, &c);
    float* p = X + (size_t)row * ((size_t)nheads * 64) + h * 64 + j;
    float x1 = p[0], x2 = p[32];
    p[0]  = x1 * c - x2 * s;
    p[32] = x2 * c + x1 * s;
}

// =================================================================
// Flash attention (fp32). One CTA: 128 query rows x one head.
// Online softmax over 64-wide key blocks; additive mask from gmem.
// Thread tile: 8 rows x 4 cols (256 threads, 16x16 layout).
// =================================================================
#define ATTN_SMEM_FLOATS (64*128 + 64*64 + 64*64 + 128*64 + 128*16 + 3*128)
#define ATTN_SMEM_BYTES  (ATTN_SMEM_FLOATS * 4)

__global__ void __launch_bounds__(256) attn_kernel(const float* __restrict__ Qg,
                                                   const float* __restrict__ Kg,
                                                   const float* __restrict__ Vg,
                                                   const float* __restrict__ Mg,
                                                   float* __restrict__ Og) {
    extern __shared__ float sm[];
    float* Qs   = sm;              // [64][128]  d-major (transposed)
    float* Ks   = Qs + 64 * 128;   // [64][64]   d-major (transposed)
    float* Vs   = Ks + 64 * 64;    // [64][64]   j-major (natural)
    float* Ps   = Vs + 64 * 64;    // [128][64]  i-major
    float* red  = Ps + 128 * 64;   // [128][16]
    float* mrow = red + 128 * 16;  // [128]
    float* lrow = mrow + 128;
    float* srow = lrow + 128;

    const int t  = threadIdx.x;
    const int tx = t & 15, ty = t >> 4;
    const int q0 = blockIdx.x * 128;
    const int h  = blockIdx.y;
    const int b  = blockIdx.z;
    const int hk = h >> 2;   // GQA: repeat_interleave -> kv head = h / 4

    const float* Qp = Qg + (size_t)b * LSEQ * D_MODEL + (size_t)h * 64;
    const float* Kp = Kg + (size_t)b * LSEQ * DKV + (size_t)hk * 64;
    const float* Vp = Vg + (size_t)b * LSEQ * DKV + (size_t)hk * 64;

    // load Q tile [128 rows x 64 dims], store transposed Qs[d][i]
#pragma unroll
    for (int e = t; e < 2048; e += 256) {
        int r  = e >> 4;
        int c4 = (e & 15) << 2;
        float4 v = *(const float4*)(Qp + (size_t)(q0 + r) * D_MODEL + c4);
        Qs[(c4 + 0) * 128 + r] = v.x;
        Qs[(c4 + 1) * 128 + r] = v.y;
        Qs[(c4 + 2) * 128 + r] = v.z;
        Qs[(c4 + 3) * 128 + r] = v.w;
    }
    if (t < 128) { mrow[t] = -3.0e38f; lrow[t] = 0.f; }

    const int i0 = ty * 8;
    const int j0 = tx * 4;   // doubles as d0 for the output

    float o[8][4];
#pragma unroll
    for (int r = 0; r < 8; r++)
#pragma unroll
        for (int c = 0; c < 4; c++) o[r][c] = 0.f;

    __syncthreads();

    for (int k0 = 0; k0 < LSEQ; k0 += 64) {
        // load K (transposed) and V (natural)
#pragma unroll
        for (int e = t; e < 1024; e += 256) {
            int r  = e >> 4;
            int c4 = (e & 15) << 2;
            float4 v = *(const float4*)(Kp + (size_t)(k0 + r) * DKV + c4);
            Ks[(c4 + 0) * 64 + r] = v.x;
            Ks[(c4 + 1) * 64 + r] = v.y;
            Ks[(c4 + 2) * 64 + r] = v.z;
            Ks[(c4 + 3) * 64 + r] = v.w;
            float4 w = *(const float4*)(Vp + (size_t)(k0 + r) * DKV + c4);
            *(float4*)&Vs[r * 64 + c4] = w;
        }
        __syncthreads();

        // S = Q K^T  (8x4 per thread)
        float s[8][4];
#pragma unroll
        for (int r = 0; r < 8; r++)
#pragma unroll
            for (int c = 0; c < 4; c++) s[r][c] = 0.f;
#pragma unroll 16
        for (int d = 0; d < 64; d++) {
            float a[8], kk[4];
            *(float4*)(a)     = *(const float4*)&Qs[d * 128 + i0];
            *(float4*)(a + 4) = *(const float4*)&Qs[d * 128 + i0 + 4];
            *(float4*)(kk)    = *(const float4*)&Ks[d * 64 + j0];
#pragma unroll
            for (int r = 0; r < 8; r++)
#pragma unroll
                for (int c = 0; c < 4; c++)
                    s[r][c] = fmaf(a[r], kk[c], s[r][c]);
        }

        // scale 1/sqrt(64), add mask, partial row max
#pragma unroll
        for (int r = 0; r < 8; r++) {
            float4 mv = *(const float4*)(Mg + (size_t)(q0 + i0 + r) * LSEQ + k0 + j0);
            s[r][0] = fmaf(s[r][0], 0.125f, mv.x);
            s[r][1] = fmaf(s[r][1], 0.125f, mv.y);
            s[r][2] = fmaf(s[r][2], 0.125f, mv.z);
            s[r][3] = fmaf(s[r][3], 0.125f, mv.w);
            float rm = fmaxf(fmaxf(s[r][0], s[r][1]), fmaxf(s[r][2], s[r][3]));
            red[(i0 + r) * 16 + tx] = rm;
        }
        __syncthreads();

        if (t < 128) {
            float mb = red[t * 16];
#pragma unroll
            for (int u = 1; u < 16; u++) mb = fmaxf(mb, red[t * 16 + u]);
            float mo = mrow[t];
            float mn = fmaxf(mo, mb);
            srow[t] = __expf(mo - mn);
            mrow[t] = mn;
        }
        __syncthreads();

        // P = exp(S - m), write to smem, partial row sums, rescale O
#pragma unroll
        for (int r = 0; r < 8; r++) {
            float mr = mrow[i0 + r];
            float p0 = __expf(s[r][0] - mr);
            float p1 = __expf(s[r][1] - mr);
            float p2 = __expf(s[r][2] - mr);
            float p3 = __expf(s[r][3] - mr);
            *(float4*)&Ps[(i0 + r) * 64 + j0] = make_float4(p0, p1, p2, p3);
            red[(i0 + r) * 16 + tx] = p0 + p1 + p2 + p3;
            float sc = srow[i0 + r];
            o[r][0] *= sc; o[r][1] *= sc; o[r][2] *= sc; o[r][3] *= sc;
        }
        __syncthreads();

        if (t < 128) {
            float sum = 0.f;
#pragma unroll
            for (int u = 0; u < 16; u++) sum += red[t * 16 + u];
            lrow[t] = lrow[t] * srow[t] + sum;
        }

        // O += P @ V  (chunks of 4 keys; broadcast float4 reads of P)
#pragma unroll 4
        for (int jc = 0; jc < 64; jc += 4) {
            float4 v0 = *(const float4*)&Vs[(jc + 0) * 64 + j0];
            float4 v1 = *(const float4*)&Vs[(jc + 1) * 64 + j0];
            float4 v2 = *(const float4*)&Vs[(jc + 2) * 64 + j0];
            float4 v3 = *(const float4*)&Vs[(jc + 3) * 64 + j0];
#pragma unroll
            for (int r = 0; r < 8; r++) {
                float4 p = *(const float4*)&Ps[(i0 + r) * 64 + jc];
                o[r][0] = fmaf(p.x, v0.x, fmaf(p.y, v1.x, fmaf(p.z, v2.x, fmaf(p.w, v3.x, o[r][0]))));
                o[r][1] = fmaf(p.x, v0.y, fmaf(p.y, v1.y, fmaf(p.z, v2.y, fmaf(p.w, v3.y, o[r][1]))));
                o[r][2] = fmaf(p.x, v0.z, fmaf(p.y, v1.z, fmaf(p.z, v2.z, fmaf(p.w, v3.z, o[r][2]))));
                o[r][3] = fmaf(p.x, v0.w, fmaf(p.y, v1.w, fmaf(p.z, v2.w, fmaf(p.w, v3.w, o[r][3]))));
            }
        }
        __syncthreads();
    }

    // normalize and store: layout [b, l, h, d] flattened -> [NROWS, 2048]
#pragma unroll
    for (int r = 0; r < 8; r++) {
        float invl = 1.0f / lrow[i0 + r];
        float4 v = make_float4(o[r][0] * invl, o[r][1] * invl, o[r][2] * invl, o[r][3] * invl);
        *(float4*)(Og + (size_t)(b * LSEQ + q0 + i0 + r) * D_MODEL + h * 64 + j0) = v;
    }
}

// =================================================================
// launch
// =================================================================
extern "C" void kernel_launch(void* const* d_in, const int* in_sizes, int n_in,
                              void* d_out, int out_size) {
    const float* x    = (const float*)d_in[0];
    const float* Wq   = (const float*)d_in[1];
    const float* Wk   = (const float*)d_in[2];
    const float* Wv   = (const float*)d_in[3];
    const float* Wo   = (const float*)d_in[4];
    const float* mask = (const float*)d_in[5];
    float* out = (float*)d_out;

    float *pQ, *pK, *pV, *pAO;
    cudaGetSymbolAddress((void**)&pQ,  g_Q);
    cudaGetSymbolAddress((void**)&pK,  g_K);
    cudaGetSymbolAddress((void**)&pV,  g_V);
    cudaGetSymbolAddress((void**)&pAO, g_AO);

    cudaFuncSetAttribute(attn_kernel, cudaFuncAttributeMaxDynamicSharedMemorySize,
                         ATTN_SMEM_BYTES);

    // Q/K/V projections: y = x @ W^T
    gemm_nt<<<dim3(D_MODEL / 128, NROWS / 128), 256>>>(x, Wq, pQ, NROWS, D_MODEL, D_MODEL);
    gemm_nt<<<dim3(DKV / 128,     NROWS / 128), 256>>>(x, Wk, pK, NROWS, DKV,     D_MODEL);
    gemm_nt<<<dim3(DKV / 128,     NROWS / 128), 256>>>(x, Wv, pV, NROWS, DKV,     D_MODEL);

    // RoPE in place
    {
        int totalQ = NROWS * 32 * 32;
        rope_kernel<<<(totalQ + 255) / 256, 256>>>(pQ, 32, totalQ);
        int totalK = NROWS * 8 * 32;
        rope_kernel<<<(totalK + 255) / 256, 256>>>(pK, 8, totalK);
    }

    // attention
    attn_kernel<<<dim3(LSEQ / 128, 32, BATCH), 256, ATTN_SMEM_BYTES>>>(pQ, pK, pV, mask, pAO);

    // output projection
    gemm_nt<<<dim3(D_MODEL / 128, NROWS / 128), 256>>>(pAO, Wo, out, NROWS, D_MODEL, D_MODEL);
}

// round 4
// speedup vs baseline: 1.5253x; 1.5253x over previous
#include <cuda_runtime.h>
#include <cuda_bf16.h>
#include <stdint.h>
#include <math.h>

#define D_MODEL 2048
#define DKV     512
#define LSEQ    2048
#define BATCH   2
#define NROWS   (BATCH * LSEQ)   // 4096

typedef __nv_bfloat16 bf16;

// -------- scratch (no allocation allowed; device globals) --------
__device__ float g_Q [(size_t)NROWS * D_MODEL];
__device__ float g_K [(size_t)NROWS * DKV];
__device__ float g_V [(size_t)NROWS * DKV];
__device__ float g_AO[(size_t)NROWS * D_MODEL];

__device__ bf16 g_xh [(size_t)NROWS * D_MODEL];
__device__ bf16 g_xl [(size_t)NROWS * D_MODEL];
__device__ bf16 g_Wqh[(size_t)D_MODEL * D_MODEL];
__device__ bf16 g_Wql[(size_t)D_MODEL * D_MODEL];
__device__ bf16 g_Wkh[(size_t)DKV * D_MODEL];
__device__ bf16 g_Wkl[(size_t)DKV * D_MODEL];
__device__ bf16 g_Wvh[(size_t)DKV * D_MODEL];
__device__ bf16 g_Wvl[(size_t)DKV * D_MODEL];
__device__ bf16 g_Woh[(size_t)D_MODEL * D_MODEL];
__device__ bf16 g_Wol[(size_t)D_MODEL * D_MODEL];
__device__ bf16 g_aoh[(size_t)NROWS * D_MODEL];
__device__ bf16 g_aol[(size_t)NROWS * D_MODEL];

// =================================================================
// PTX helpers (sm_80+ subset: mma.sync / ldmatrix / cp.async)
// =================================================================
__device__ __forceinline__ uint32_t smem_u32(const void* p) {
    uint32_t a;
    asm("{ .reg .u64 t; cvta.to.shared.u64 t, %1; cvt.u32.u64 %0, t; }" : "=r"(a) : "l"(p));
    return a;
}

__device__ __forceinline__ void cp16(uint32_t dst, const void* src) {
    asm volatile("cp.async.cg.shared.global [%0], [%1], 16;" :: "r"(dst), "l"(src) : "memory");
}
__device__ __forceinline__ void cp_commit() {
    asm volatile("cp.async.commit_group;" ::: "memory");
}
template <int N>
__device__ __forceinline__ void cp_wait() {
    asm volatile("cp.async.wait_group %0;" :: "n"(N) : "memory");
}

__device__ __forceinline__ void ldsm_x4(uint32_t* r, uint32_t addr) {
    asm volatile("ldmatrix.sync.aligned.m8n8.x4.shared.b16 {%0,%1,%2,%3}, [%4];"
                 : "=r"(r[0]), "=r"(r[1]), "=r"(r[2]), "=r"(r[3]) : "r"(addr));
}

__device__ __forceinline__ void mma_bf16(float* c, const uint32_t* a, const uint32_t* b) {
    asm volatile(
        "mma.sync.aligned.m16n8k16.row.col.f32.bf16.bf16.f32 "
        "{%0,%1,%2,%3}, {%4,%5,%6,%7}, {%8,%9}, {%0,%1,%2,%3};"
        : "+f"(c[0]), "+f"(c[1]), "+f"(c[2]), "+f"(c[3])
        : "r"(a[0]), "r"(a[1]), "r"(a[2]), "r"(a[3]), "r"(b[0]), "r"(b[1]));
}

// =================================================================
// split: fp32 -> bf16 hi + bf16 lo  (x = hi + lo)
// =================================================================
__global__ void split_bf16(const float* __restrict__ in,
                           bf16* __restrict__ hi, bf16* __restrict__ lo, int n4) {
    int i = blockIdx.x * blockDim.x + threadIdx.x;
    if (i >= n4) return;
    float4 x = ((const float4*)in)[i];
    bf16 h0 = __float2bfloat16(x.x), h1 = __float2bfloat16(x.y);
    bf16 h2 = __float2bfloat16(x.z), h3 = __float2bfloat16(x.w);
    bf16 l0 = __float2bfloat16(x.x - __bfloat162float(h0));
    bf16 l1 = __float2bfloat16(x.y - __bfloat162float(h1));
    bf16 l2 = __float2bfloat16(x.z - __bfloat162float(h2));
    bf16 l3 = __float2bfloat16(x.w - __bfloat162float(h3));
    __nv_bfloat162 hh0; hh0.x = h0; hh0.y = h1;
    __nv_bfloat162 hh1; hh1.x = h2; hh1.y = h3;
    __nv_bfloat162 ll0; ll0.x = l0; ll0.y = l1;
    __nv_bfloat162 ll1; ll1.x = l2; ll1.y = l3;
    ((__nv_bfloat162*)hi)[2 * i]     = hh0;
    ((__nv_bfloat162*)hi)[2 * i + 1] = hh1;
    ((__nv_bfloat162*)lo)[2 * i]     = ll0;
    ((__nv_bfloat162*)lo)[2 * i + 1] = ll1;
}

// =================================================================
// HMMA GEMM: C[M,N] = (Ah+Al)[M,K] @ (Bh+Bl)[N,K]^T  (fp32 out)
// 128x128 block, BK=32, 8 warps (each 32Mx64N), bf16-split 3-product.
// cp.async double-buffered SMEM, 80B padded rows (ldmatrix conflict-free).
// =================================================================
#define GPAD        80                      // bytes per 32-bf16 row (padded)
#define GTILE_BYTES (128 * GPAD)            // 10240 per array
#define GSTAGE      (4 * GTILE_BYTES)       // Ah,Al,Bh,Bl
#define GEMM_SMEM_BYTES (2 * GSTAGE)        // 81920

__global__ void __launch_bounds__(256) gemm_mma(const bf16* __restrict__ Ah,
                                                const bf16* __restrict__ Al,
                                                const bf16* __restrict__ Bh,
                                                const bf16* __restrict__ Bl,
                                                float* __restrict__ C,
                                                int M, int N, int K) {
    extern __shared__ char dsm[];
    const uint32_t sb0 = smem_u32(dsm);

    const int t    = threadIdx.x;
    const int wid  = t >> 5;
    const int lane = t & 31;
    const int wm   = wid & 3;       // 4 warps over M (32 rows each)
    const int wn   = wid >> 2;      // 2 warps over N (64 cols each)
    const int m0   = blockIdx.y * 128;
    const int n0   = blockIdx.x * 128;

    const bf16* gbase[4] = { Ah + (size_t)m0 * K, Al + (size_t)m0 * K,
                             Bh + (size_t)n0 * K, Bl + (size_t)n0 * K };

    float acc[2][8][4];
#pragma unroll
    for (int i = 0; i < 2; i++)
#pragma unroll
        for (int j = 0; j < 8; j++)
#pragma unroll
            for (int c = 0; c < 4; c++) acc[i][j][c] = 0.f;

    const int niter = K >> 5;   // BK = 32

    // async stage loader: 4 arrays x 128 rows x 4 chunks of 16B
    auto load_stage = [&](int it, int s) {
        const int kt = it << 5;
        const uint32_t sb = sb0 + s * GSTAGE;
#pragma unroll
        for (int u = 0; u < 8; u++) {
            int e   = t + 256 * u;        // 0..2047
            int arr = e >> 9;
            int idx = e & 511;
            int row = idx >> 2;
            int ch  = idx & 3;
            cp16(sb + arr * GTILE_BYTES + row * GPAD + ch * 16,
                 gbase[arr] + (size_t)row * K + kt + ch * 8);
        }
        cp_commit();
    };

    load_stage(0, 0);
    if (niter > 1) load_stage(1, 1);
    cp_wait<1>();
    __syncthreads();

    // ldmatrix lane addressing
    const int r8  = lane & 7;
    const int sel = lane >> 3;
    const int aro = wm * 32 + ((sel & 1) << 3) + r8;     // + mt*16
    const int aco = (sel >> 1) << 3;                     // + kof
    const int bro = wn * 64 + ((sel >> 1) << 3) + r8;    // + nt2*16
    const int bco = (sel & 1) << 3;                      // + kof

    for (int it = 0; it < niter; it++) {
        const int s = it & 1;
        const uint32_t sb = sb0 + s * GSTAGE;
#pragma unroll
        for (int ks = 0; ks < 2; ks++) {
            const int kof = ks << 4;
            uint32_t aH[2][4], aL[2][4];
#pragma unroll
            for (int mt = 0; mt < 2; mt++) {
                uint32_t aaddr = sb + (aro + mt * 16) * GPAD + (aco + kof) * 2;
                ldsm_x4(aH[mt], aaddr);
                ldsm_x4(aL[mt], aaddr + GTILE_BYTES);
            }
#pragma unroll
            for (int nt2 = 0; nt2 < 4; nt2++) {
                uint32_t baddr = sb + 2 * GTILE_BYTES
                               + (bro + nt2 * 16) * GPAD + (bco + kof) * 2;
                uint32_t bH[4], bL[4];
                ldsm_x4(bH, baddr);
                ldsm_x4(bL, baddr + GTILE_BYTES);
#pragma unroll
                for (int mt = 0; mt < 2; mt++) {
                    mma_bf16(acc[mt][2 * nt2],     aH[mt], bH);
                    mma_bf16(acc[mt][2 * nt2],     aH[mt], bL);
                    mma_bf16(acc[mt][2 * nt2],     aL[mt], bH);
                    mma_bf16(acc[mt][2 * nt2 + 1], aH[mt], bH + 2);
                    mma_bf16(acc[mt][2 * nt2 + 1], aH[mt], bL + 2);
                    mma_bf16(acc[mt][2 * nt2 + 1], aL[mt], bH + 2);
                }
            }
        }
        __syncthreads();                 // everyone done reading buf s
        if (it + 2 < niter) {
            load_stage(it + 2, s);
            cp_wait<1>();
        } else {
            cp_wait<0>();
        }
        __syncthreads();
    }

    // epilogue
    const int erow = lane >> 2;
    const int ecol = (lane & 3) << 1;
#pragma unroll
    for (int mt = 0; mt < 2; mt++) {
#pragma unroll
        for (int nt = 0; nt < 8; nt++) {
            int row = m0 + wm * 32 + mt * 16 + erow;
            int col = n0 + wn * 64 + nt * 8 + ecol;
            *(float2*)(C + (size_t)row * N + col)       = make_float2(acc[mt][nt][0], acc[mt][nt][1]);
            *(float2*)(C + (size_t)(row + 8) * N + col) = make_float2(acc[mt][nt][2], acc[mt][nt][3]);
        }
    }
}

// =================================================================
// RoPE (in place). X is [NROWS, nheads*64]; position = row % LSEQ.
// =================================================================
__global__ void rope_kernel(float* __restrict__ X, int nheads, int total) {
    int idx = blockIdx.x * blockDim.x + threadIdx.x;
    if (idx >= total) return;
    int j   = idx & 31;
    int h   = (idx >> 5) % nheads;
    int row = idx / (nheads * 32);
    int l   = row & (LSEQ - 1);
    float inv = 1.0f / powf(10000.0f, (float)j * (1.0f / 32.0f));
    float ang = (float)l * inv;
    float s, c;
    sincosf(ang, &s, &c);
    float* p = X + (size_t)row * ((size_t)nheads * 64) + h * 64 + j;
    float x1 = p[0], x2 = p[32];
    p[0]  = x1 * c - x2 * s;
    p[32] = x2 * c + x1 * s;
}

// =================================================================
// Flash attention (fp32) — unchanged from R1 (at FFMA roofline)
// =================================================================
#define ATTN_SMEM_FLOATS (64*128 + 64*64 + 64*64 + 128*64 + 128*16 + 3*128)
#define ATTN_SMEM_BYTES  (ATTN_SMEM_FLOATS * 4)

__global__ void __launch_bounds__(256) attn_kernel(const float* __restrict__ Qg,
                                                   const float* __restrict__ Kg,
                                                   const float* __restrict__ Vg,
                                                   const float* __restrict__ Mg,
                                                   float* __restrict__ Og) {
    extern __shared__ float sm[];
    float* Qs   = sm;
    float* Ks   = Qs + 64 * 128;
    float* Vs   = Ks + 64 * 64;
    float* Ps   = Vs + 64 * 64;
    float* red  = Ps + 128 * 64;
    float* mrow = red + 128 * 16;
    float* lrow = mrow + 128;
    float* srow = lrow + 128;

    const int t  = threadIdx.x;
    const int tx = t & 15, ty = t >> 4;
    const int q0 = blockIdx.x * 128;
    const int h  = blockIdx.y;
    const int b  = blockIdx.z;
    const int hk = h >> 2;

    const float* Qp = Qg + (size_t)b * LSEQ * D_MODEL + (size_t)h * 64;
    const float* Kp = Kg + (size_t)b * LSEQ * DKV + (size_t)hk * 64;
    const float* Vp = Vg + (size_t)b * LSEQ * DKV + (size_t)hk * 64;

#pragma unroll
    for (int e = t; e < 2048; e += 256) {
        int r  = e >> 4;
        int c4 = (e & 15) << 2;
        float4 v = *(const float4*)(Qp + (size_t)(q0 + r) * D_MODEL + c4);
        Qs[(c4 + 0) * 128 + r] = v.x;
        Qs[(c4 + 1) * 128 + r] = v.y;
        Qs[(c4 + 2) * 128 + r] = v.z;
        Qs[(c4 + 3) * 128 + r] = v.w;
    }
    if (t < 128) { mrow[t] = -3.0e38f; lrow[t] = 0.f; }

    const int i0 = ty * 8;
    const int j0 = tx * 4;

    float o[8][4];
#pragma unroll
    for (int r = 0; r < 8; r++)
#pragma unroll
        for (int c = 0; c < 4; c++) o[r][c] = 0.f;

    __syncthreads();

    for (int k0 = 0; k0 < LSEQ; k0 += 64) {
#pragma unroll
        for (int e = t; e < 1024; e += 256) {
            int r  = e >> 4;
            int c4 = (e & 15) << 2;
            float4 v = *(const float4*)(Kp + (size_t)(k0 + r) * DKV + c4);
            Ks[(c4 + 0) * 64 + r] = v.x;
            Ks[(c4 + 1) * 64 + r] = v.y;
            Ks[(c4 + 2) * 64 + r] = v.z;
            Ks[(c4 + 3) * 64 + r] = v.w;
            float4 w = *(const float4*)(Vp + (size_t)(k0 + r) * DKV + c4);
            *(float4*)&Vs[r * 64 + c4] = w;
        }
        __syncthreads();

        float s[8][4];
#pragma unroll
        for (int r = 0; r < 8; r++)
#pragma unroll
            for (int c = 0; c < 4; c++) s[r][c] = 0.f;
#pragma unroll 16
        for (int d = 0; d < 64; d++) {
            float a[8], kk[4];
            *(float4*)(a)     = *(const float4*)&Qs[d * 128 + i0];
            *(float4*)(a + 4) = *(const float4*)&Qs[d * 128 + i0 + 4];
            *(float4*)(kk)    = *(const float4*)&Ks[d * 64 + j0];
#pragma unroll
            for (int r = 0; r < 8; r++)
#pragma unroll
                for (int c = 0; c < 4; c++)
                    s[r][c] = fmaf(a[r], kk[c], s[r][c]);
        }

#pragma unroll
        for (int r = 0; r < 8; r++) {
            float4 mv = *(const float4*)(Mg + (size_t)(q0 + i0 + r) * LSEQ + k0 + j0);
            s[r][0] = fmaf(s[r][0], 0.125f, mv.x);
            s[r][1] = fmaf(s[r][1], 0.125f, mv.y);
            s[r][2] = fmaf(s[r][2], 0.125f, mv.z);
            s[r][3] = fmaf(s[r][3], 0.125f, mv.w);
            float rm = fmaxf(fmaxf(s[r][0], s[r][1]), fmaxf(s[r][2], s[r][3]));
            red[(i0 + r) * 16 + tx] = rm;
        }
        __syncthreads();

        if (t < 128) {
            float mb = red[t * 16];
#pragma unroll
            for (int u = 1; u < 16; u++) mb = fmaxf(mb, red[t * 16 + u]);
            float mo = mrow[t];
            float mn = fmaxf(mo, mb);
            srow[t] = __expf(mo - mn);
            mrow[t] = mn;
        }
        __syncthreads();

#pragma unroll
        for (int r = 0; r < 8; r++) {
            float mr = mrow[i0 + r];
            float p0 = __expf(s[r][0] - mr);
            float p1 = __expf(s[r][1] - mr);
            float p2 = __expf(s[r][2] - mr);
            float p3 = __expf(s[r][3] - mr);
            *(float4*)&Ps[(i0 + r) * 64 + j0] = make_float4(p0, p1, p2, p3);
            red[(i0 + r) * 16 + tx] = p0 + p1 + p2 + p3;
            float sc = srow[i0 + r];
            o[r][0] *= sc; o[r][1] *= sc; o[r][2] *= sc; o[r][3] *= sc;
        }
        __syncthreads();

        if (t < 128) {
            float sum = 0.f;
#pragma unroll
            for (int u = 0; u < 16; u++) sum += red[t * 16 + u];
            lrow[t] = lrow[t] * srow[t] + sum;
        }

#pragma unroll 4
        for (int jc = 0; jc < 64; jc += 4) {
            float4 v0 = *(const float4*)&Vs[(jc + 0) * 64 + j0];
            float4 v1 = *(const float4*)&Vs[(jc + 1) * 64 + j0];
            float4 v2 = *(const float4*)&Vs[(jc + 2) * 64 + j0];
            float4 v3 = *(const float4*)&Vs[(jc + 3) * 64 + j0];
#pragma unroll
            for (int r = 0; r < 8; r++) {
                float4 p = *(const float4*)&Ps[(i0 + r) * 64 + jc];
                o[r][0] = fmaf(p.x, v0.x, fmaf(p.y, v1.x, fmaf(p.z, v2.x, fmaf(p.w, v3.x, o[r][0]))));
                o[r][1] = fmaf(p.x, v0.y, fmaf(p.y, v1.y, fmaf(p.z, v2.y, fmaf(p.w, v3.y, o[r][1]))));
                o[r][2] = fmaf(p.x, v0.z, fmaf(p.y, v1.z, fmaf(p.z, v2.z, fmaf(p.w, v3.z, o[r][2]))));
                o[r][3] = fmaf(p.x, v0.w, fmaf(p.y, v1.w, fmaf(p.z, v2.w, fmaf(p.w, v3.w, o[r][3]))));
            }
        }
        __syncthreads();
    }

#pragma unroll
    for (int r = 0; r < 8; r++) {
        float invl = 1.0f / lrow[i0 + r];
        float4 v = make_float4(o[r][0] * invl, o[r][1] * invl, o[r][2] * invl, o[r][3] * invl);
        *(float4*)(Og + (size_t)(b * LSEQ + q0 + i0 + r) * D_MODEL + h * 64 + j0) = v;
    }
}

// =================================================================
// launch
// =================================================================
extern "C" void kernel_launch(void* const* d_in, const int* in_sizes, int n_in,
                              void* d_out, int out_size) {
    const float* x    = (const float*)d_in[0];
    const float* Wq   = (const float*)d_in[1];
    const float* Wk   = (const float*)d_in[2];
    const float* Wv   = (const float*)d_in[3];
    const float* Wo   = (const float*)d_in[4];
    const float* mask = (const float*)d_in[5];
    float* out = (float*)d_out;

    float *pQ, *pK, *pV, *pAO;
    bf16 *pxh, *pxl, *pWqh, *pWql, *pWkh, *pWkl, *pWvh, *pWvl, *pWoh, *pWol, *paoh, *paol;
    cudaGetSymbolAddress((void**)&pQ,  g_Q);
    cudaGetSymbolAddress((void**)&pK,  g_K);
    cudaGetSymbolAddress((void**)&pV,  g_V);
    cudaGetSymbolAddress((void**)&pAO, g_AO);
    cudaGetSymbolAddress((void**)&pxh, g_xh);   cudaGetSymbolAddress((void**)&pxl, g_xl);
    cudaGetSymbolAddress((void**)&pWqh, g_Wqh); cudaGetSymbolAddress((void**)&pWql, g_Wql);
    cudaGetSymbolAddress((void**)&pWkh, g_Wkh); cudaGetSymbolAddress((void**)&pWkl, g_Wkl);
    cudaGetSymbolAddress((void**)&pWvh, g_Wvh); cudaGetSymbolAddress((void**)&pWvl, g_Wvl);
    cudaGetSymbolAddress((void**)&pWoh, g_Woh); cudaGetSymbolAddress((void**)&pWol, g_Wol);
    cudaGetSymbolAddress((void**)&paoh, g_aoh); cudaGetSymbolAddress((void**)&paol, g_aol);

    cudaFuncSetAttribute(attn_kernel, cudaFuncAttributeMaxDynamicSharedMemorySize,
                         ATTN_SMEM_BYTES);
    cudaFuncSetAttribute(gemm_mma, cudaFuncAttributeMaxDynamicSharedMemorySize,
                         GEMM_SMEM_BYTES);

    // split inputs/weights to bf16 hi/lo
    {
        int n;
        n = NROWS * D_MODEL / 4;   split_bf16<<<(n + 255) / 256, 256>>>(x,  pxh,  pxl,  n);
        n = D_MODEL * D_MODEL / 4; split_bf16<<<(n + 255) / 256, 256>>>(Wq, pWqh, pWql, n);
        n = DKV * D_MODEL / 4;     split_bf16<<<(n + 255) / 256, 256>>>(Wk, pWkh, pWkl, n);
        n = DKV * D_MODEL / 4;     split_bf16<<<(n + 255) / 256, 256>>>(Wv, pWvh, pWvl, n);
        n = D_MODEL * D_MODEL / 4; split_bf16<<<(n + 255) / 256, 256>>>(Wo, pWoh, pWol, n);
    }

    // Q/K/V projections on tensor cores (HMMA)
    gemm_mma<<<dim3(D_MODEL / 128, NROWS / 128), 256, GEMM_SMEM_BYTES>>>(
        pxh, pxl, pWqh, pWql, pQ, NROWS, D_MODEL, D_MODEL);
    gemm_mma<<<dim3(DKV / 128, NROWS / 128), 256, GEMM_SMEM_BYTES>>>(
        pxh, pxl, pWkh, pWkl, pK, NROWS, DKV, D_MODEL);
    gemm_mma<<<dim3(DKV / 128, NROWS / 128), 256, GEMM_SMEM_BYTES>>>(
        pxh, pxl, pWvh, pWvl, pV, NROWS, DKV, D_MODEL);

    // RoPE in place
    {
        int totalQ = NROWS * 32 * 32;
        rope_kernel<<<(totalQ + 255) / 256, 256>>>(pQ, 32, totalQ);
        int totalK = NROWS * 8 * 32;
        rope_kernel<<<(totalK + 255) / 256, 256>>>(pK, 8, totalK);
    }

    // attention (fp32, FFMA-roofline)
    attn_kernel<<<dim3(LSEQ / 128, 32, BATCH), 256, ATTN_SMEM_BYTES>>>(pQ, pK, pV, mask, pAO);

    // split attention output, then O projection
    {
        int n = NROWS * D_MODEL / 4;
        split_bf16<<<(n + 255) / 256, 256>>>(pAO, paoh, paol, n);
    }
    gemm_mma<<<dim3(D_MODEL / 128, NROWS / 128), 256, GEMM_SMEM_BYTES>>>(
        paoh, paol, pWoh, pWol, out, NROWS, D_MODEL, D_MODEL);
}

// round 5
// speedup vs baseline: 1.9346x; 1.2684x over previous
#include <cuda_runtime.h>
#include <cuda_bf16.h>
#include <stdint.h>
#include <math.h>

#define D_MODEL 2048
#define DKV     512
#define LSEQ    2048
#define BATCH   2
#define NROWS   (BATCH * LSEQ)   // 4096
#define QBLKS   (LSEQ / 128)     // 16
#define KBLKS   (LSEQ / 64)      // 32

typedef __nv_bfloat16 bf16;

// -------- scratch (no allocation allowed; device globals) --------
__device__ float g_Q [(size_t)NROWS * D_MODEL];
__device__ float g_K [(size_t)NROWS * DKV];
__device__ float g_V [(size_t)NROWS * DKV];
__device__ float g_AO[(size_t)NROWS * D_MODEL];
__device__ int   g_active[QBLKS * KBLKS];

__device__ bf16 g_xh [(size_t)NROWS * D_MODEL];
__device__ bf16 g_xl [(size_t)NROWS * D_MODEL];
__device__ bf16 g_Wqh[(size_t)D_MODEL * D_MODEL];
__device__ bf16 g_Wql[(size_t)D_MODEL * D_MODEL];
__device__ bf16 g_Wkh[(size_t)DKV * D_MODEL];
__device__ bf16 g_Wkl[(size_t)DKV * D_MODEL];
__device__ bf16 g_Wvh[(size_t)DKV * D_MODEL];
__device__ bf16 g_Wvl[(size_t)DKV * D_MODEL];
__device__ bf16 g_Woh[(size_t)D_MODEL * D_MODEL];
__device__ bf16 g_Wol[(size_t)D_MODEL * D_MODEL];
__device__ bf16 g_aoh[(size_t)NROWS * D_MODEL];
__device__ bf16 g_aol[(size_t)NROWS * D_MODEL];

// =================================================================
// PTX helpers (sm_80+ subset: mma.sync / ldmatrix / cp.async)
// =================================================================
__device__ __forceinline__ uint32_t smem_u32(const void* p) {
    uint32_t a;
    asm("{ .reg .u64 t; cvta.to.shared.u64 t, %1; cvt.u32.u64 %0, t; }" : "=r"(a) : "l"(p));
    return a;
}

__device__ __forceinline__ void cp16(uint32_t dst, const void* src) {
    asm volatile("cp.async.cg.shared.global [%0], [%1], 16;" :: "r"(dst), "l"(src) : "memory");
}
__device__ __forceinline__ void cp_commit() {
    asm volatile("cp.async.commit_group;" ::: "memory");
}
template <int N>
__device__ __forceinline__ void cp_wait() {
    asm volatile("cp.async.wait_group %0;" :: "n"(N) : "memory");
}

__device__ __forceinline__ void ldsm_x4(uint32_t* r, uint32_t addr) {
    asm volatile("ldmatrix.sync.aligned.m8n8.x4.shared.b16 {%0,%1,%2,%3}, [%4];"
                 : "=r"(r[0]), "=r"(r[1]), "=r"(r[2]), "=r"(r[3]) : "r"(addr));
}

__device__ __forceinline__ void mma_bf16(float* c, const uint32_t* a, const uint32_t* b) {
    asm volatile(
        "mma.sync.aligned.m16n8k16.row.col.f32.bf16.bf16.f32 "
        "{%0,%1,%2,%3}, {%4,%5,%6,%7}, {%8,%9}, {%0,%1,%2,%3};"
        : "+f"(c[0]), "+f"(c[1]), "+f"(c[2]), "+f"(c[3])
        : "r"(a[0]), "r"(a[1]), "r"(a[2]), "r"(a[3]), "r"(b[0]), "r"(b[1]));
}

// =================================================================
// split: fp32 -> bf16 hi + bf16 lo  (x = hi + lo)
// =================================================================
__global__ void split_bf16(const float* __restrict__ in,
                           bf16* __restrict__ hi, bf16* __restrict__ lo, int n4) {
    int i = blockIdx.x * blockDim.x + threadIdx.x;
    if (i >= n4) return;
    float4 x = ((const float4*)in)[i];
    bf16 h0 = __float2bfloat16(x.x), h1 = __float2bfloat16(x.y);
    bf16 h2 = __float2bfloat16(x.z), h3 = __float2bfloat16(x.w);
    bf16 l0 = __float2bfloat16(x.x - __bfloat162float(h0));
    bf16 l1 = __float2bfloat16(x.y - __bfloat162float(h1));
    bf16 l2 = __float2bfloat16(x.z - __bfloat162float(h2));
    bf16 l3 = __float2bfloat16(x.w - __bfloat162float(h3));
    __nv_bfloat162 hh0; hh0.x = h0; hh0.y = h1;
    __nv_bfloat162 hh1; hh1.x = h2; hh1.y = h3;
    __nv_bfloat162 ll0; ll0.x = l0; ll0.y = l1;
    __nv_bfloat162 ll1; ll1.x = l2; ll1.y = l3;
    ((__nv_bfloat162*)hi)[2 * i]     = hh0;
    ((__nv_bfloat162*)hi)[2 * i + 1] = hh1;
    ((__nv_bfloat162*)lo)[2 * i]     = ll0;
    ((__nv_bfloat162*)lo)[2 * i + 1] = ll1;
}

// =================================================================
// mask block-max: active[qb][kb] = (max over 128x64 block) > -1e8
// =================================================================
__global__ void maskmax_kernel(const float* __restrict__ M, int* __restrict__ act) {
    __shared__ float red[256];
    const int qb = blockIdx.x, kb = blockIdx.y;
    const int t = threadIdx.x;
    float mx = -3.0e38f;
    for (int e = t; e < 128 * 64 / 4; e += 256) {
        int r = e >> 4;            // 0..127
        int c = (e & 15) << 2;     // 0..60 step 4
        float4 v = *(const float4*)(M + (size_t)(qb * 128 + r) * LSEQ + kb * 64 + c);
        mx = fmaxf(mx, fmaxf(fmaxf(v.x, v.y), fmaxf(v.z, v.w)));
    }
    red[t] = mx;
    __syncthreads();
    for (int s = 128; s > 0; s >>= 1) {
        if (t < s) red[t] = fmaxf(red[t], red[t + s]);
        __syncthreads();
    }
    if (t == 0) act[qb * KBLKS + kb] = (red[0] > -1.0e8f) ? 1 : 0;
}

// =================================================================
// HMMA GEMM: C[M,N] = (Ah+Al)[M,K] @ (Bh+Bl)[N,K]^T  (fp32 out)
// =================================================================
#define GPAD        80
#define GTILE_BYTES (128 * GPAD)
#define GSTAGE      (4 * GTILE_BYTES)
#define GEMM_SMEM_BYTES (2 * GSTAGE)

__global__ void __launch_bounds__(256) gemm_mma(const bf16* __restrict__ Ah,
                                                const bf16* __restrict__ Al,
                                                const bf16* __restrict__ Bh,
                                                const bf16* __restrict__ Bl,
                                                float* __restrict__ C,
                                                int M, int N, int K) {
    extern __shared__ char dsm[];
    const uint32_t sb0 = smem_u32(dsm);

    const int t    = threadIdx.x;
    const int wid  = t >> 5;
    const int lane = t & 31;
    const int wm   = wid & 3;
    const int wn   = wid >> 2;
    const int m0   = blockIdx.y * 128;
    const int n0   = blockIdx.x * 128;

    const bf16* gbase[4] = { Ah + (size_t)m0 * K, Al + (size_t)m0 * K,
                             Bh + (size_t)n0 * K, Bl + (size_t)n0 * K };

    float acc[2][8][4];
#pragma unroll
    for (int i = 0; i < 2; i++)
#pragma unroll
        for (int j = 0; j < 8; j++)
#pragma unroll
            for (int c = 0; c < 4; c++) acc[i][j][c] = 0.f;

    const int niter = K >> 5;

    auto load_stage = [&](int it, int s) {
        const int kt = it << 5;
        const uint32_t sb = sb0 + s * GSTAGE;
#pragma unroll
        for (int u = 0; u < 8; u++) {
            int e   = t + 256 * u;
            int arr = e >> 9;
            int idx = e & 511;
            int row = idx >> 2;
            int ch  = idx & 3;
            cp16(sb + arr * GTILE_BYTES + row * GPAD + ch * 16,
                 gbase[arr] + (size_t)row * K + kt + ch * 8);
        }
        cp_commit();
    };

    load_stage(0, 0);
    if (niter > 1) load_stage(1, 1);
    cp_wait<1>();
    __syncthreads();

    const int r8  = lane & 7;
    const int sel = lane >> 3;
    const int aro = wm * 32 + ((sel & 1) << 3) + r8;
    const int aco = (sel >> 1) << 3;
    const int bro = wn * 64 + ((sel >> 1) << 3) + r8;
    const int bco = (sel & 1) << 3;

    for (int it = 0; it < niter; it++) {
        const int s = it & 1;
        const uint32_t sb = sb0 + s * GSTAGE;
#pragma unroll
        for (int ks = 0; ks < 2; ks++) {
            const int kof = ks << 4;
            uint32_t aH[2][4], aL[2][4];
#pragma unroll
            for (int mt = 0; mt < 2; mt++) {
                uint32_t aaddr = sb + (aro + mt * 16) * GPAD + (aco + kof) * 2;
                ldsm_x4(aH[mt], aaddr);
                ldsm_x4(aL[mt], aaddr + GTILE_BYTES);
            }
#pragma unroll
            for (int nt2 = 0; nt2 < 4; nt2++) {
                uint32_t baddr = sb + 2 * GTILE_BYTES
                               + (bro + nt2 * 16) * GPAD + (bco + kof) * 2;
                uint32_t bH[4], bL[4];
                ldsm_x4(bH, baddr);
                ldsm_x4(bL, baddr + GTILE_BYTES);
#pragma unroll
                for (int mt = 0; mt < 2; mt++) {
                    mma_bf16(acc[mt][2 * nt2],     aH[mt], bH);
                    mma_bf16(acc[mt][2 * nt2],     aH[mt], bL);
                    mma_bf16(acc[mt][2 * nt2],     aL[mt], bH);
                    mma_bf16(acc[mt][2 * nt2 + 1], aH[mt], bH + 2);
                    mma_bf16(acc[mt][2 * nt2 + 1], aH[mt], bL + 2);
                    mma_bf16(acc[mt][2 * nt2 + 1], aL[mt], bH + 2);
                }
            }
        }
        __syncthreads();
        if (it + 2 < niter) {
            load_stage(it + 2, s);
            cp_wait<1>();
        } else {
            cp_wait<0>();
        }
        __syncthreads();
    }

    const int erow = lane >> 2;
    const int ecol = (lane & 3) << 1;
#pragma unroll
    for (int mt = 0; mt < 2; mt++) {
#pragma unroll
        for (int nt = 0; nt < 8; nt++) {
            int row = m0 + wm * 32 + mt * 16 + erow;
            int col = n0 + wn * 64 + nt * 8 + ecol;
            *(float2*)(C + (size_t)row * N + col)       = make_float2(acc[mt][nt][0], acc[mt][nt][1]);
            *(float2*)(C + (size_t)(row + 8) * N + col) = make_float2(acc[mt][nt][2], acc[mt][nt][3]);
        }
    }
}

// =================================================================
// RoPE (in place)
// =================================================================
__global__ void rope_kernel(float* __restrict__ X, int nheads, int total) {
    int idx = blockIdx.x * blockDim.x + threadIdx.x;
    if (idx >= total) return;
    int j   = idx & 31;
    int h   = (idx >> 5) % nheads;
    int row = idx / (nheads * 32);
    int l   = row & (LSEQ - 1);
    float inv = 1.0f / powf(10000.0f, (float)j * (1.0f / 32.0f));
    float ang = (float)l * inv;
    float s, c;
    sincosf(ang, &s, &c);
    float* p = X + (size_t)row * ((size_t)nheads * 64) + h * 64 + j;
    float x1 = p[0], x2 = p[32];
    p[0]  = x1 * c - x2 * s;
    p[32] = x2 * c + x1 * s;
}

// =================================================================
// Flash attention (fp32) with mask-driven block skipping
// =================================================================
#define ATTN_SMEM_FLOATS (64*128 + 64*64 + 64*64 + 128*64 + 128*16 + 3*128)
#define ATTN_SMEM_BYTES  (ATTN_SMEM_FLOATS * 4)

__global__ void __launch_bounds__(256) attn_kernel(const float* __restrict__ Qg,
                                                   const float* __restrict__ Kg,
                                                   const float* __restrict__ Vg,
                                                   const float* __restrict__ Mg,
                                                   const int* __restrict__ act,
                                                   float* __restrict__ Og) {
    extern __shared__ float sm[];
    float* Qs   = sm;
    float* Ks   = Qs + 64 * 128;
    float* Vs   = Ks + 64 * 64;
    float* Ps   = Vs + 64 * 64;
    float* red  = Ps + 128 * 64;
    float* mrow = red + 128 * 16;
    float* lrow = mrow + 128;
    float* srow = lrow + 128;

    const int t  = threadIdx.x;
    const int tx = t & 15, ty = t >> 4;
    const int qb = blockIdx.x;
    const int q0 = qb * 128;
    const int h  = blockIdx.y;
    const int b  = blockIdx.z;
    const int hk = h >> 2;

    const float* Qp = Qg + (size_t)b * LSEQ * D_MODEL + (size_t)h * 64;
    const float* Kp = Kg + (size_t)b * LSEQ * DKV + (size_t)hk * 64;
    const float* Vp = Vg + (size_t)b * LSEQ * DKV + (size_t)hk * 64;

#pragma unroll
    for (int e = t; e < 2048; e += 256) {
        int r  = e >> 4;
        int c4 = (e & 15) << 2;
        float4 v = *(const float4*)(Qp + (size_t)(q0 + r) * D_MODEL + c4);
        Qs[(c4 + 0) * 128 + r] = v.x;
        Qs[(c4 + 1) * 128 + r] = v.y;
        Qs[(c4 + 2) * 128 + r] = v.z;
        Qs[(c4 + 3) * 128 + r] = v.w;
    }
    if (t < 128) { mrow[t] = -3.0e38f; lrow[t] = 0.f; }

    const int i0 = ty * 8;
    const int j0 = tx * 4;

    float o[8][4];
#pragma unroll
    for (int r = 0; r < 8; r++)
#pragma unroll
        for (int c = 0; c < 4; c++) o[r][c] = 0.f;

    __syncthreads();

    for (int kb = 0; kb < KBLKS; kb++) {
        if (!act[qb * KBLKS + kb]) continue;   // fully-masked block: exp -> 0
        const int k0 = kb * 64;
#pragma unroll
        for (int e = t; e < 1024; e += 256) {
            int r  = e >> 4;
            int c4 = (e & 15) << 2;
            float4 v = *(const float4*)(Kp + (size_t)(k0 + r) * DKV + c4);
            Ks[(c4 + 0) * 64 + r] = v.x;
            Ks[(c4 + 1) * 64 + r] = v.y;
            Ks[(c4 + 2) * 64 + r] = v.z;
            Ks[(c4 + 3) * 64 + r] = v.w;
            float4 w = *(const float4*)(Vp + (size_t)(k0 + r) * DKV + c4);
            *(float4*)&Vs[r * 64 + c4] = w;
        }
        __syncthreads();

        float s[8][4];
#pragma unroll
        for (int r = 0; r < 8; r++)
#pragma unroll
            for (int c = 0; c < 4; c++) s[r][c] = 0.f;
#pragma unroll 16
        for (int d = 0; d < 64; d++) {
            float a[8], kk[4];
            *(float4*)(a)     = *(const float4*)&Qs[d * 128 + i0];
            *(float4*)(a + 4) = *(const float4*)&Qs[d * 128 + i0 + 4];
            *(float4*)(kk)    = *(const float4*)&Ks[d * 64 + j0];
#pragma unroll
            for (int r = 0; r < 8; r++)
#pragma unroll
                for (int c = 0; c < 4; c++)
                    s[r][c] = fmaf(a[r], kk[c], s[r][c]);
        }

#pragma unroll
        for (int r = 0; r < 8; r++) {
            float4 mv = *(const float4*)(Mg + (size_t)(q0 + i0 + r) * LSEQ + k0 + j0);
            s[r][0] = fmaf(s[r][0], 0.125f, mv.x);
            s[r][1] = fmaf(s[r][1], 0.125f, mv.y);
            s[r][2] = fmaf(s[r][2], 0.125f, mv.z);
            s[r][3] = fmaf(s[r][3], 0.125f, mv.w);
            float rm = fmaxf(fmaxf(s[r][0], s[r][1]), fmaxf(s[r][2], s[r][3]));
            red[(i0 + r) * 16 + tx] = rm;
        }
        __syncthreads();

        if (t < 128) {
            float mb = red[t * 16];
#pragma unroll
            for (int u = 1; u < 16; u++) mb = fmaxf(mb, red[t * 16 + u]);
            float mo = mrow[t];
            float mn = fmaxf(mo, mb);
            srow[t] = __expf(mo - mn);
            mrow[t] = mn;
        }
        __syncthreads();

#pragma unroll
        for (int r = 0; r < 8; r++) {
            float mr = mrow[i0 + r];
            float p0 = __expf(s[r][0] - mr);
            float p1 = __expf(s[r][1] - mr);
            float p2 = __expf(s[r][2] - mr);
            float p3 = __expf(s[r][3] - mr);
            *(float4*)&Ps[(i0 + r) * 64 + j0] = make_float4(p0, p1, p2, p3);
            red[(i0 + r) * 16 + tx] = p0 + p1 + p2 + p3;
            float sc = srow[i0 + r];
            o[r][0] *= sc; o[r][1] *= sc; o[r][2] *= sc; o[r][3] *= sc;
        }
        __syncthreads();

        if (t < 128) {
            float sum = 0.f;
#pragma unroll
            for (int u = 0; u < 16; u++) sum += red[t * 16 + u];
            lrow[t] = lrow[t] * srow[t] + sum;
        }

#pragma unroll 4
        for (int jc = 0; jc < 64; jc += 4) {
            float4 v0 = *(const float4*)&Vs[(jc + 0) * 64 + j0];
            float4 v1 = *(const float4*)&Vs[(jc + 1) * 64 + j0];
            float4 v2 = *(const float4*)&Vs[(jc + 2) * 64 + j0];
            float4 v3 = *(const float4*)&Vs[(jc + 3) * 64 + j0];
#pragma unroll
            for (int r = 0; r < 8; r++) {
                float4 p = *(const float4*)&Ps[(i0 + r) * 64 + jc];
                o[r][0] = fmaf(p.x, v0.x, fmaf(p.y, v1.x, fmaf(p.z, v2.x, fmaf(p.w, v3.x, o[r][0]))));
                o[r][1] = fmaf(p.x, v0.y, fmaf(p.y, v1.y, fmaf(p.z, v2.y, fmaf(p.w, v3.y, o[r][1]))));
                o[r][2] = fmaf(p.x, v0.z, fmaf(p.y, v1.z, fmaf(p.z, v2.z, fmaf(p.w, v3.z, o[r][2]))));
                o[r][3] = fmaf(p.x, v0.w, fmaf(p.y, v1.w, fmaf(p.z, v2.w, fmaf(p.w, v3.w, o[r][3]))));
            }
        }
        __syncthreads();
    }

#pragma unroll
    for (int r = 0; r < 8; r++) {
        float invl = 1.0f / lrow[i0 + r];
        float4 v = make_float4(o[r][0] * invl, o[r][1] * invl, o[r][2] * invl, o[r][3] * invl);
        *(float4*)(Og + (size_t)(b * LSEQ + q0 + i0 + r) * D_MODEL + h * 64 + j0) = v;
    }
}

// =================================================================
// launch
// =================================================================
extern "C" void kernel_launch(void* const* d_in, const int* in_sizes, int n_in,
                              void* d_out, int out_size) {
    const float* x    = (const float*)d_in[0];
    const float* Wq   = (const float*)d_in[1];
    const float* Wk   = (const float*)d_in[2];
    const float* Wv   = (const float*)d_in[3];
    const float* Wo   = (const float*)d_in[4];
    const float* mask = (const float*)d_in[5];
    float* out = (float*)d_out;

    float *pQ, *pK, *pV, *pAO;
    int* pact;
    bf16 *pxh, *pxl, *pWqh, *pWql, *pWkh, *pWkl, *pWvh, *pWvl, *pWoh, *pWol, *paoh, *paol;
    cudaGetSymbolAddress((void**)&pQ,  g_Q);
    cudaGetSymbolAddress((void**)&pK,  g_K);
    cudaGetSymbolAddress((void**)&pV,  g_V);
    cudaGetSymbolAddress((void**)&pAO, g_AO);
    cudaGetSymbolAddress((void**)&pact, g_active);
    cudaGetSymbolAddress((void**)&pxh, g_xh);   cudaGetSymbolAddress((void**)&pxl, g_xl);
    cudaGetSymbolAddress((void**)&pWqh, g_Wqh); cudaGetSymbolAddress((void**)&pWql, g_Wql);
    cudaGetSymbolAddress((void**)&pWkh, g_Wkh); cudaGetSymbolAddress((void**)&pWkl, g_Wkl);
    cudaGetSymbolAddress((void**)&pWvh, g_Wvh); cudaGetSymbolAddress((void**)&pWvl, g_Wvl);
    cudaGetSymbolAddress((void**)&pWoh, g_Woh); cudaGetSymbolAddress((void**)&pWol, g_Wol);
    cudaGetSymbolAddress((void**)&paoh, g_aoh); cudaGetSymbolAddress((void**)&paol, g_aol);

    cudaFuncSetAttribute(attn_kernel, cudaFuncAttributeMaxDynamicSharedMemorySize,
                         ATTN_SMEM_BYTES);
    cudaFuncSetAttribute(gemm_mma, cudaFuncAttributeMaxDynamicSharedMemorySize,
                         GEMM_SMEM_BYTES);

    // split inputs/weights to bf16 hi/lo + mask block-max table
    {
        int n;
        n = NROWS * D_MODEL / 4;   split_bf16<<<(n + 255) / 256, 256>>>(x,  pxh,  pxl,  n);
        n = D_MODEL * D_MODEL / 4; split_bf16<<<(n + 255) / 256, 256>>>(Wq, pWqh, pWql, n);
        n = DKV * D_MODEL / 4;     split_bf16<<<(n + 255) / 256, 256>>>(Wk, pWkh, pWkl, n);
        n = DKV * D_MODEL / 4;     split_bf16<<<(n + 255) / 256, 256>>>(Wv, pWvh, pWvl, n);
        n = D_MODEL * D_MODEL / 4; split_bf16<<<(n + 255) / 256, 256>>>(Wo, pWoh, pWol, n);
        maskmax_kernel<<<dim3(QBLKS, KBLKS), 256>>>(mask, pact);
    }

    // Q/K/V projections on tensor cores (HMMA)
    gemm_mma<<<dim3(D_MODEL / 128, NROWS / 128), 256, GEMM_SMEM_BYTES>>>(
        pxh, pxl, pWqh, pWql, pQ, NROWS, D_MODEL, D_MODEL);
    gemm_mma<<<dim3(DKV / 128, NROWS / 128), 256, GEMM_SMEM_BYTES>>>(
        pxh, pxl, pWkh, pWkl, pK, NROWS, DKV, D_MODEL);
    gemm_mma<<<dim3(DKV / 128, NROWS / 128), 256, GEMM_SMEM_BYTES>>>(
        pxh, pxl, pWvh, pWvl, pV, NROWS, DKV, D_MODEL);

    // RoPE in place
    {
        int totalQ = NROWS * 32 * 32;
        rope_kernel<<<(totalQ + 255) / 256, 256>>>(pQ, 32, totalQ);
        int totalK = NROWS * 8 * 32;
        rope_kernel<<<(totalK + 255) / 256, 256>>>(pK, 8, totalK);
    }

    // attention (fp32, block-skipping)
    attn_kernel<<<dim3(QBLKS, 32, BATCH), 256, ATTN_SMEM_BYTES>>>(pQ, pK, pV, mask, pact, pAO);

    // split attention output, then O projection
    {
        int n = NROWS * D_MODEL / 4;
        split_bf16<<<(n + 255) / 256, 256>>>(pAO, paoh, paol, n);
    }
    gemm_mma<<<dim3(D_MODEL / 128, NROWS / 128), 256, GEMM_SMEM_BYTES>>>(
        paoh, paol, pWoh, pWol, out, NROWS, D_MODEL, D_MODEL);
}

// round 6
// speedup vs baseline: 2.8148x; 1.4549x over previous
#include <cuda_runtime.h>
#include <cuda_bf16.h>
#include <stdint.h>
#include <math.h>

#define D_MODEL 2048
#define DKV     512
#define LSEQ    2048
#define BATCH   2
#define NROWS   (BATCH * LSEQ)   // 4096
#define QBLKS   (LSEQ / 128)     // 16
#define KBLKS   (LSEQ / 64)      // 32

typedef __nv_bfloat16 bf16;

// -------- scratch (no allocation allowed; device globals) --------
__device__ float g_Q [(size_t)NROWS * D_MODEL];
__device__ float g_K [(size_t)NROWS * DKV];
__device__ float g_V [(size_t)NROWS * DKV];
__device__ float g_AO[(size_t)NROWS * D_MODEL];
__device__ int   g_active[QBLKS * KBLKS];

__device__ bf16 g_xh [(size_t)NROWS * D_MODEL];
__device__ bf16 g_xl [(size_t)NROWS * D_MODEL];
__device__ bf16 g_Wqh[(size_t)D_MODEL * D_MODEL];
__device__ bf16 g_Wql[(size_t)D_MODEL * D_MODEL];
__device__ bf16 g_Wkh[(size_t)DKV * D_MODEL];
__device__ bf16 g_Wkl[(size_t)DKV * D_MODEL];
__device__ bf16 g_Wvh[(size_t)DKV * D_MODEL];
__device__ bf16 g_Wvl[(size_t)DKV * D_MODEL];
__device__ bf16 g_Woh[(size_t)D_MODEL * D_MODEL];
__device__ bf16 g_Wol[(size_t)D_MODEL * D_MODEL];
__device__ bf16 g_aoh[(size_t)NROWS * D_MODEL];
__device__ bf16 g_aol[(size_t)NROWS * D_MODEL];

// bf16 splits of rope'd Q, K and of V
__device__ bf16 g_Qh[(size_t)NROWS * D_MODEL];
__device__ bf16 g_Ql[(size_t)NROWS * D_MODEL];
__device__ bf16 g_Kh[(size_t)NROWS * DKV];
__device__ bf16 g_Kl[(size_t)NROWS * DKV];
__device__ bf16 g_Vh[(size_t)NROWS * DKV];
__device__ bf16 g_Vl[(size_t)NROWS * DKV];

// =================================================================
// PTX helpers (sm_80+ subset: mma.sync / ldmatrix / cp.async)
// =================================================================
__device__ __forceinline__ uint32_t smem_u32(const void* p) {
    uint32_t a;
    asm("{ .reg .u64 t; cvta.to.shared.u64 t, %1; cvt.u32.u64 %0, t; }" : "=r"(a) : "l"(p));
    return a;
}

__device__ __forceinline__ void cp16(uint32_t dst, const void* src) {
    asm volatile("cp.async.cg.shared.global [%0], [%1], 16;" :: "r"(dst), "l"(src) : "memory");
}
__device__ __forceinline__ void cp_commit() {
    asm volatile("cp.async.commit_group;" ::: "memory");
}
template <int N>
__device__ __forceinline__ void cp_wait() {
    asm volatile("cp.async.wait_group %0;" :: "n"(N) : "memory");
}

__device__ __forceinline__ void ldsm_x4(uint32_t* r, uint32_t addr) {
    asm volatile("ldmatrix.sync.aligned.m8n8.x4.shared.b16 {%0,%1,%2,%3}, [%4];"
                 : "=r"(r[0]), "=r"(r[1]), "=r"(r[2]), "=r"(r[3]) : "r"(addr));
}
__device__ __forceinline__ void ldsm_x4_t(uint32_t* r, uint32_t addr) {
    asm volatile("ldmatrix.sync.aligned.m8n8.x4.trans.shared.b16 {%0,%1,%2,%3}, [%4];"
                 : "=r"(r[0]), "=r"(r[1]), "=r"(r[2]), "=r"(r[3]) : "r"(addr));
}

__device__ __forceinline__ void mma_bf16(float* c, const uint32_t* a, const uint32_t* b) {
    asm volatile(
        "mma.sync.aligned.m16n8k16.row.col.f32.bf16.bf16.f32 "
        "{%0,%1,%2,%3}, {%4,%5,%6,%7}, {%8,%9}, {%0,%1,%2,%3};"
        : "+f"(c[0]), "+f"(c[1]), "+f"(c[2]), "+f"(c[3])
        : "r"(a[0]), "r"(a[1]), "r"(a[2]), "r"(a[3]), "r"(b[0]), "r"(b[1]));
}

__device__ __forceinline__ uint32_t pack_bf16x2(float lo, float hi) {
    uint32_t r;
    asm("cvt.rn.bf16x2.f32 %0, %1, %2;" : "=r"(r) : "f"(hi), "f"(lo));
    return r;
}
__device__ __forceinline__ float bf16lo_f(uint32_t r) { return __uint_as_float(r << 16); }
__device__ __forceinline__ float bf16hi_f(uint32_t r) { return __uint_as_float(r & 0xffff0000u); }

// =================================================================
// split: fp32 -> bf16 hi + bf16 lo  (x = hi + lo)
// =================================================================
__global__ void split_bf16(const float* __restrict__ in,
                           bf16* __restrict__ hi, bf16* __restrict__ lo, int n4) {
    int i = blockIdx.x * blockDim.x + threadIdx.x;
    if (i >= n4) return;
    float4 x = ((const float4*)in)[i];
    bf16 h0 = __float2bfloat16(x.x), h1 = __float2bfloat16(x.y);
    bf16 h2 = __float2bfloat16(x.z), h3 = __float2bfloat16(x.w);
    bf16 l0 = __float2bfloat16(x.x - __bfloat162float(h0));
    bf16 l1 = __float2bfloat16(x.y - __bfloat162float(h1));
    bf16 l2 = __float2bfloat16(x.z - __bfloat162float(h2));
    bf16 l3 = __float2bfloat16(x.w - __bfloat162float(h3));
    __nv_bfloat162 hh0; hh0.x = h0; hh0.y = h1;
    __nv_bfloat162 hh1; hh1.x = h2; hh1.y = h3;
    __nv_bfloat162 ll0; ll0.x = l0; ll0.y = l1;
    __nv_bfloat162 ll1; ll1.x = l2; ll1.y = l3;
    ((__nv_bfloat162*)hi)[2 * i]     = hh0;
    ((__nv_bfloat162*)hi)[2 * i + 1] = hh1;
    ((__nv_bfloat162*)lo)[2 * i]     = ll0;
    ((__nv_bfloat162*)lo)[2 * i + 1] = ll1;
}

// =================================================================
// mask block-max: active[qb][kb] = (max over 128x64 block) > -1e8
// =================================================================
__global__ void maskmax_kernel(const float* __restrict__ M, int* __restrict__ act) {
    __shared__ float red[256];
    const int qb = blockIdx.x, kb = blockIdx.y;
    const int t = threadIdx.x;
    float mx = -3.0e38f;
    for (int e = t; e < 128 * 64 / 4; e += 256) {
        int r = e >> 4;
        int c = (e & 15) << 2;
        float4 v = *(const float4*)(M + (size_t)(qb * 128 + r) * LSEQ + kb * 64 + c);
        mx = fmaxf(mx, fmaxf(fmaxf(v.x, v.y), fmaxf(v.z, v.w)));
    }
    red[t] = mx;
    __syncthreads();
    for (int s = 128; s > 0; s >>= 1) {
        if (t < s) red[t] = fmaxf(red[t], red[t + s]);
        __syncthreads();
    }
    if (t == 0) act[qb * KBLKS + kb] = (red[0] > -1.0e8f) ? 1 : 0;
}

// =================================================================
// HMMA GEMM: C[M,N] = (Ah+Al)[M,K] @ (Bh+Bl)[N,K]^T  (fp32 out)
// =================================================================
#define GPAD        80
#define GTILE_BYTES (128 * GPAD)
#define GSTAGE      (4 * GTILE_BYTES)
#define GEMM_SMEM_BYTES (2 * GSTAGE)

__global__ void __launch_bounds__(256) gemm_mma(const bf16* __restrict__ Ah,
                                                const bf16* __restrict__ Al,
                                                const bf16* __restrict__ Bh,
                                                const bf16* __restrict__ Bl,
                                                float* __restrict__ C,
                                                int M, int N, int K) {
    extern __shared__ char dsm[];
    const uint32_t sb0 = smem_u32(dsm);

    const int t    = threadIdx.x;
    const int wid  = t >> 5;
    const int lane = t & 31;
    const int wm   = wid & 3;
    const int wn   = wid >> 2;
    const int m0   = blockIdx.y * 128;
    const int n0   = blockIdx.x * 128;

    const bf16* gbase[4] = { Ah + (size_t)m0 * K, Al + (size_t)m0 * K,
                             Bh + (size_t)n0 * K, Bl + (size_t)n0 * K };

    float acc[2][8][4];
#pragma unroll
    for (int i = 0; i < 2; i++)
#pragma unroll
        for (int j = 0; j < 8; j++)
#pragma unroll
            for (int c = 0; c < 4; c++) acc[i][j][c] = 0.f;

    const int niter = K >> 5;

    auto load_stage = [&](int it, int s) {
        const int kt = it << 5;
        const uint32_t sb = sb0 + s * GSTAGE;
#pragma unroll
        for (int u = 0; u < 8; u++) {
            int e   = t + 256 * u;
            int arr = e >> 9;
            int idx = e & 511;
            int row = idx >> 2;
            int ch  = idx & 3;
            cp16(sb + arr * GTILE_BYTES + row * GPAD + ch * 16,
                 gbase[arr] + (size_t)row * K + kt + ch * 8);
        }
        cp_commit();
    };

    load_stage(0, 0);
    if (niter > 1) load_stage(1, 1);
    cp_wait<1>();
    __syncthreads();

    const int r8  = lane & 7;
    const int sel = lane >> 3;
    const int aro = wm * 32 + ((sel & 1) << 3) + r8;
    const int aco = (sel >> 1) << 3;
    const int bro = wn * 64 + ((sel >> 1) << 3) + r8;
    const int bco = (sel & 1) << 3;

    for (int it = 0; it < niter; it++) {
        const int s = it & 1;
        const uint32_t sb = sb0 + s * GSTAGE;
#pragma unroll
        for (int ks = 0; ks < 2; ks++) {
            const int kof = ks << 4;
            uint32_t aH[2][4], aL[2][4];
#pragma unroll
            for (int mt = 0; mt < 2; mt++) {
                uint32_t aaddr = sb + (aro + mt * 16) * GPAD + (aco + kof) * 2;
                ldsm_x4(aH[mt], aaddr);
                ldsm_x4(aL[mt], aaddr + GTILE_BYTES);
            }
#pragma unroll
            for (int nt2 = 0; nt2 < 4; nt2++) {
                uint32_t baddr = sb + 2 * GTILE_BYTES
                               + (bro + nt2 * 16) * GPAD + (bco + kof) * 2;
                uint32_t bH[4], bL[4];
                ldsm_x4(bH, baddr);
                ldsm_x4(bL, baddr + GTILE_BYTES);
#pragma unroll
                for (int mt = 0; mt < 2; mt++) {
                    mma_bf16(acc[mt][2 * nt2],     aH[mt], bH);
                    mma_bf16(acc[mt][2 * nt2],     aH[mt], bL);
                    mma_bf16(acc[mt][2 * nt2],     aL[mt], bH);
                    mma_bf16(acc[mt][2 * nt2 + 1], aH[mt], bH + 2);
                    mma_bf16(acc[mt][2 * nt2 + 1], aH[mt], bL + 2);
                    mma_bf16(acc[mt][2 * nt2 + 1], aL[mt], bH + 2);
                }
            }
        }
        __syncthreads();
        if (it + 2 < niter) {
            load_stage(it + 2, s);
            cp_wait<1>();
        } else {
            cp_wait<0>();
        }
        __syncthreads();
    }

    const int erow = lane >> 2;
    const int ecol = (lane & 3) << 1;
#pragma unroll
    for (int mt = 0; mt < 2; mt++) {
#pragma unroll
        for (int nt = 0; nt < 8; nt++) {
            int row = m0 + wm * 32 + mt * 16 + erow;
            int col = n0 + wn * 64 + nt * 8 + ecol;
            *(float2*)(C + (size_t)row * N + col)       = make_float2(acc[mt][nt][0], acc[mt][nt][1]);
            *(float2*)(C + (size_t)(row + 8) * N + col) = make_float2(acc[mt][nt][2], acc[mt][nt][3]);
        }
    }
}

// =================================================================
// RoPE (in place)
// =================================================================
__global__ void rope_kernel(float* __restrict__ X, int nheads, int total) {
    int idx = blockIdx.x * blockDim.x + threadIdx.x;
    if (idx >= total) return;
    int j   = idx & 31;
    int h   = (idx >> 5) % nheads;
    int row = idx / (nheads * 32);
    int l   = row & (LSEQ - 1);
    float inv = 1.0f / powf(10000.0f, (float)j * (1.0f / 32.0f));
    float ang = (float)l * inv;
    float s, c;
    sincosf(ang, &s, &c);
    float* p = X + (size_t)row * ((size_t)nheads * 64) + h * 64 + j;
    float x1 = p[0], x2 = p[32];
    p[0]  = x1 * c - x2 * s;
    p[32] = x2 * c + x1 * s;
}

// =================================================================
// HMMA flash attention, bf16-split, register softmax.
// CTA = 128 q-rows x one (b,h); 8 warps x 16 rows.
// =================================================================
#define VPITCH     144                 // bytes per 64-bf16 row (padded)
#define ATILE      (64 * VPITCH)       // 9216 per K/V array
#define ASTAGE     (4 * ATILE)         // Kh,Kl,Vh,Vl = 36864
#define ATTN_SMEM  (2 * ASTAGE + 256)  // + active list

__global__ void __launch_bounds__(256) attn_mma(const bf16* __restrict__ Qhp,
                                                const bf16* __restrict__ Qlp,
                                                const bf16* __restrict__ Khp,
                                                const bf16* __restrict__ Klp,
                                                const bf16* __restrict__ Vhp,
                                                const bf16* __restrict__ Vlp,
                                                const float* __restrict__ Mg,
                                                const int* __restrict__ act,
                                                float* __restrict__ Og) {
    extern __shared__ char sm8[];
    int* slist = (int*)(sm8 + 2 * ASTAGE);
    const uint32_t sb0 = smem_u32(sm8);

    const int t    = threadIdx.x;
    const int lane = t & 31;
    const int w    = t >> 5;
    const int qb   = blockIdx.x, q0 = qb * 128;
    const int h    = blockIdx.y, b = blockIdx.z, hk = h >> 2;

    if (t == 0) {
        int n = 0;
        for (int kb = 0; kb < KBLKS; kb++)
            if (act[qb * KBLKS + kb]) slist[n++] = kb;
        slist[32] = n;
    }

    // ---- stage Q (128 rows x 64 bf16, hi+lo) into smem, then to regs ----
    const bf16* qgh = Qhp + (size_t)(b * LSEQ + q0) * D_MODEL + h * 64;
    const bf16* qgl = Qlp + (size_t)(b * LSEQ + q0) * D_MODEL + h * 64;
#pragma unroll
    for (int u = 0; u < 4; u++) {
        int e = t + 256 * u;          // 0..1023
        int row = e >> 3, ch = e & 7;
        cp16(sb0 + row * VPITCH + ch * 16,          qgh + (size_t)row * D_MODEL + ch * 8);
        cp16(sb0 + 2 * ATILE + row * VPITCH + ch * 16, qgl + (size_t)row * D_MODEL + ch * 8);
    }
    cp_commit();
    cp_wait<0>();
    __syncthreads();

    const int r8  = lane & 7;
    const int sel = lane >> 3;
    const int gr  = lane >> 2;
    const int gc2 = (lane & 3) << 1;

    uint32_t aH[4][4], aL[4][4];
    {
        const int aro = w * 16 + ((sel & 1) << 3) + r8;
        const int aco = (sel >> 1) << 3;
#pragma unroll
        for (int ks = 0; ks < 4; ks++) {
            uint32_t ad = sb0 + aro * VPITCH + (aco + ks * 16) * 2;
            ldsm_x4(aH[ks], ad);
            ldsm_x4(aL[ks], ad + 2 * ATILE);
        }
    }
    __syncthreads();   // Q regs loaded; smem reusable, slist visible

    const int nact = slist[32];

    const bf16* kbase_h = Khp + (size_t)(b * LSEQ) * DKV + hk * 64;
    const bf16* kbase_l = Klp + (size_t)(b * LSEQ) * DKV + hk * 64;
    const bf16* vbase_h = Vhp + (size_t)(b * LSEQ) * DKV + hk * 64;
    const bf16* vbase_l = Vlp + (size_t)(b * LSEQ) * DKV + hk * 64;

    auto stage = [&](int i, int s) {
        const int k0 = slist[i] * 64;
        const uint32_t sb = sb0 + s * ASTAGE;
        const bf16* bases[4] = { kbase_h + (size_t)k0 * DKV, kbase_l + (size_t)k0 * DKV,
                                 vbase_h + (size_t)k0 * DKV, vbase_l + (size_t)k0 * DKV };
#pragma unroll
        for (int u = 0; u < 8; u++) {
            int e   = t + 256 * u;    // 0..2047
            int arr = e >> 9;
            int idx = e & 511;
            int row = idx >> 3, ch = idx & 7;
            cp16(sb + arr * ATILE + row * VPITCH + ch * 16,
                 bases[arr] + (size_t)row * DKV + ch * 8);
        }
        cp_commit();
    };

    float o[8][4];
#pragma unroll
    for (int j = 0; j < 8; j++)
#pragma unroll
        for (int c = 0; c < 4; c++) o[j][c] = 0.f;
    float m0r = -1.0e30f, m1r = -1.0e30f, l0r = 0.f, l1r = 0.f;

    stage(0, 0);
    if (nact > 1) stage(1, 1);

    const float* mrowb = Mg + (size_t)(q0 + w * 16 + gr) * LSEQ + gc2;

    for (int i = 0; i < nact; i++) {
        const int s  = i & 1;
        const int k0 = slist[i] * 64;
        const uint32_t sb  = sb0 + s * ASTAGE;

        if (i + 1 < nact) cp_wait<1>(); else cp_wait<0>();
        __syncthreads();

        // ---- S = Q K^T (split, 3 products) ----
        float sfr[8][4];
#pragma unroll
        for (int j = 0; j < 8; j++)
#pragma unroll
            for (int c = 0; c < 4; c++) sfr[j][c] = 0.f;
#pragma unroll
        for (int ks = 0; ks < 4; ks++) {
#pragma unroll
            for (int nt2 = 0; nt2 < 4; nt2++) {
                uint32_t kaddr = sb + (nt2 * 16 + ((sel >> 1) << 3) + r8) * VPITCH
                               + (ks * 16 + ((sel & 1) << 3)) * 2;
                uint32_t bH[4], bL[4];
                ldsm_x4(bH, kaddr);
                ldsm_x4(bL, kaddr + ATILE);
                mma_bf16(sfr[2 * nt2],     aH[ks], bH);
                mma_bf16(sfr[2 * nt2],     aH[ks], bL);
                mma_bf16(sfr[2 * nt2],     aL[ks], bH);
                mma_bf16(sfr[2 * nt2 + 1], aH[ks], bH + 2);
                mma_bf16(sfr[2 * nt2 + 1], aH[ks], bL + 2);
                mma_bf16(sfr[2 * nt2 + 1], aL[ks], bH + 2);
            }
        }

        // ---- scale + mask + register softmax ----
        const float* m0p = mrowb + k0;
        const float* m1p = m0p + 8 * LSEQ;
        float mx0 = -1.0e30f, mx1 = -1.0e30f;
#pragma unroll
        for (int j = 0; j < 8; j++) {
            float2 u0 = *(const float2*)(m0p + 8 * j);
            float2 u1 = *(const float2*)(m1p + 8 * j);
            sfr[j][0] = fmaf(sfr[j][0], 0.125f, u0.x);
            sfr[j][1] = fmaf(sfr[j][1], 0.125f, u0.y);
            sfr[j][2] = fmaf(sfr[j][2], 0.125f, u1.x);
            sfr[j][3] = fmaf(sfr[j][3], 0.125f, u1.y);
            mx0 = fmaxf(mx0, fmaxf(sfr[j][0], sfr[j][1]));
            mx1 = fmaxf(mx1, fmaxf(sfr[j][2], sfr[j][3]));
        }
        mx0 = fmaxf(mx0, __shfl_xor_sync(0xffffffffu, mx0, 1));
        mx0 = fmaxf(mx0, __shfl_xor_sync(0xffffffffu, mx0, 2));
        mx1 = fmaxf(mx1, __shfl_xor_sync(0xffffffffu, mx1, 1));
        mx1 = fmaxf(mx1, __shfl_xor_sync(0xffffffffu, mx1, 2));

        float mn0 = fmaxf(m0r, mx0), mn1 = fmaxf(m1r, mx1);
        float sc0 = __expf(m0r - mn0), sc1 = __expf(m1r - mn1);
        m0r = mn0; m1r = mn1;

        uint32_t paH[4][4], paL[4][4];
        float sum0 = 0.f, sum1 = 0.f;
#pragma unroll
        for (int j = 0; j < 8; j++) {
            float p0 = __expf(sfr[j][0] - mn0);
            float p1 = __expf(sfr[j][1] - mn0);
            float p2 = __expf(sfr[j][2] - mn1);
            float p3 = __expf(sfr[j][3] - mn1);
            sum0 += p0 + p1;
            sum1 += p2 + p3;
            uint32_t h01 = pack_bf16x2(p0, p1);
            uint32_t h23 = pack_bf16x2(p2, p3);
            uint32_t lo01 = pack_bf16x2(p0 - bf16lo_f(h01), p1 - bf16hi_f(h01));
            uint32_t lo23 = pack_bf16x2(p2 - bf16lo_f(h23), p3 - bf16hi_f(h23));
            int ks = j >> 1;
            int sl = (j & 1) << 1;
            paH[ks][sl]     = h01;
            paH[ks][sl + 1] = h23;
            paL[ks][sl]     = lo01;
            paL[ks][sl + 1] = lo23;
        }
        sum0 += __shfl_xor_sync(0xffffffffu, sum0, 1);
        sum0 += __shfl_xor_sync(0xffffffffu, sum0, 2);
        sum1 += __shfl_xor_sync(0xffffffffu, sum1, 1);
        sum1 += __shfl_xor_sync(0xffffffffu, sum1, 2);
        l0r = l0r * sc0 + sum0;
        l1r = l1r * sc1 + sum1;
#pragma unroll
        for (int j = 0; j < 8; j++) {
            o[j][0] *= sc0; o[j][1] *= sc0;
            o[j][2] *= sc1; o[j][3] *= sc1;
        }

        // ---- O += P V (split, 3 products); V via ldmatrix.trans ----
        const uint32_t sv = sb + 2 * ATILE;
#pragma unroll
        for (int ks = 0; ks < 4; ks++) {
#pragma unroll
            for (int nt2 = 0; nt2 < 4; nt2++) {
                uint32_t vaddr = sv + (ks * 16 + ((sel & 1) << 3) + r8) * VPITCH
                               + (nt2 * 16 + ((sel >> 1) << 3)) * 2;
                uint32_t vH[4], vL[4];
                ldsm_x4_t(vH, vaddr);
                ldsm_x4_t(vL, vaddr + ATILE);
                mma_bf16(o[2 * nt2],     paH[ks], vH);
                mma_bf16(o[2 * nt2],     paH[ks], vL);
                mma_bf16(o[2 * nt2],     paL[ks], vH);
                mma_bf16(o[2 * nt2 + 1], paH[ks], vH + 2);
                mma_bf16(o[2 * nt2 + 1], paH[ks], vL + 2);
                mma_bf16(o[2 * nt2 + 1], paL[ks], vH + 2);
            }
        }
        __syncthreads();
        if (i + 2 < nact) stage(i + 2, s);
    }

    // ---- normalize + store ----
    float inv0 = 1.0f / l0r, inv1 = 1.0f / l1r;
    float* o0 = Og + (size_t)(b * LSEQ + q0 + w * 16 + gr) * D_MODEL + h * 64 + gc2;
    float* o1 = o0 + (size_t)8 * D_MODEL;
#pragma unroll
    for (int j = 0; j < 8; j++) {
        *(float2*)(o0 + 8 * j) = make_float2(o[j][0] * inv0, o[j][1] * inv0);
        *(float2*)(o1 + 8 * j) = make_float2(o[j][2] * inv1, o[j][3] * inv1);
    }
}

// =================================================================
// launch
// =================================================================
extern "C" void kernel_launch(void* const* d_in, const int* in_sizes, int n_in,
                              void* d_out, int out_size) {
    const float* x    = (const float*)d_in[0];
    const float* Wq   = (const float*)d_in[1];
    const float* Wk   = (const float*)d_in[2];
    const float* Wv   = (const float*)d_in[3];
    const float* Wo   = (const float*)d_in[4];
    const float* mask = (const float*)d_in[5];
    float* out = (float*)d_out;

    float *pQ, *pK, *pV, *pAO;
    int* pact;
    bf16 *pxh, *pxl, *pWqh, *pWql, *pWkh, *pWkl, *pWvh, *pWvl, *pWoh, *pWol, *paoh, *paol;
    bf16 *pQh, *pQl, *pKh, *pKl, *pVh, *pVl;
    cudaGetSymbolAddress((void**)&pQ,  g_Q);
    cudaGetSymbolAddress((void**)&pK,  g_K);
    cudaGetSymbolAddress((void**)&pV,  g_V);
    cudaGetSymbolAddress((void**)&pAO, g_AO);
    cudaGetSymbolAddress((void**)&pact, g_active);
    cudaGetSymbolAddress((void**)&pxh, g_xh);   cudaGetSymbolAddress((void**)&pxl, g_xl);
    cudaGetSymbolAddress((void**)&pWqh, g_Wqh); cudaGetSymbolAddress((void**)&pWql, g_Wql);
    cudaGetSymbolAddress((void**)&pWkh, g_Wkh); cudaGetSymbolAddress((void**)&pWkl, g_Wkl);
    cudaGetSymbolAddress((void**)&pWvh, g_Wvh); cudaGetSymbolAddress((void**)&pWvl, g_Wvl);
    cudaGetSymbolAddress((void**)&pWoh, g_Woh); cudaGetSymbolAddress((void**)&pWol, g_Wol);
    cudaGetSymbolAddress((void**)&paoh, g_aoh); cudaGetSymbolAddress((void**)&paol, g_aol);
    cudaGetSymbolAddress((void**)&pQh, g_Qh);   cudaGetSymbolAddress((void**)&pQl, g_Ql);
    cudaGetSymbolAddress((void**)&pKh, g_Kh);   cudaGetSymbolAddress((void**)&pKl, g_Kl);
    cudaGetSymbolAddress((void**)&pVh, g_Vh);   cudaGetSymbolAddress((void**)&pVl, g_Vl);

    cudaFuncSetAttribute(attn_mma, cudaFuncAttributeMaxDynamicSharedMemorySize,
                         ATTN_SMEM);
    cudaFuncSetAttribute(gemm_mma, cudaFuncAttributeMaxDynamicSharedMemorySize,
                         GEMM_SMEM_BYTES);

    // split inputs/weights to bf16 hi/lo + mask block-max table
    {
        int n;
        n = NROWS * D_MODEL / 4;   split_bf16<<<(n + 255) / 256, 256>>>(x,  pxh,  pxl,  n);
        n = D_MODEL * D_MODEL / 4; split_bf16<<<(n + 255) / 256, 256>>>(Wq, pWqh, pWql, n);
        n = DKV * D_MODEL / 4;     split_bf16<<<(n + 255) / 256, 256>>>(Wk, pWkh, pWkl, n);
        n = DKV * D_MODEL / 4;     split_bf16<<<(n + 255) / 256, 256>>>(Wv, pWvh, pWvl, n);
        n = D_MODEL * D_MODEL / 4; split_bf16<<<(n + 255) / 256, 256>>>(Wo, pWoh, pWol, n);
        maskmax_kernel<<<dim3(QBLKS, KBLKS), 256>>>(mask, pact);
    }

    // Q/K/V projections on tensor cores (HMMA)
    gemm_mma<<<dim3(D_MODEL / 128, NROWS / 128), 256, GEMM_SMEM_BYTES>>>(
        pxh, pxl, pWqh, pWql, pQ, NROWS, D_MODEL, D_MODEL);
    gemm_mma<<<dim3(DKV / 128, NROWS / 128), 256, GEMM_SMEM_BYTES>>>(
        pxh, pxl, pWkh, pWkl, pK, NROWS, DKV, D_MODEL);
    gemm_mma<<<dim3(DKV / 128, NROWS / 128), 256, GEMM_SMEM_BYTES>>>(
        pxh, pxl, pWvh, pWvl, pV, NROWS, DKV, D_MODEL);

    // RoPE in place
    {
        int totalQ = NROWS * 32 * 32;
        rope_kernel<<<(totalQ + 255) / 256, 256>>>(pQ, 32, totalQ);
        int totalK = NROWS * 8 * 32;
        rope_kernel<<<(totalK + 255) / 256, 256>>>(pK, 8, totalK);
    }

    // bf16 splits of rope'd Q, K and of V
    {
        int n;
        n = NROWS * D_MODEL / 4; split_bf16<<<(n + 255) / 256, 256>>>(pQ, pQh, pQl, n);
        n = NROWS * DKV / 4;     split_bf16<<<(n + 255) / 256, 256>>>(pK, pKh, pKl, n);
        n = NROWS * DKV / 4;     split_bf16<<<(n + 255) / 256, 256>>>(pV, pVh, pVl, n);
    }

    // attention (HMMA split, block-skipping)
    attn_mma<<<dim3(QBLKS, 32, BATCH), 256, ATTN_SMEM>>>(
        pQh, pQl, pKh, pKl, pVh, pVl, mask, pact, pAO);

    // split attention output, then O projection
    {
        int n = NROWS * D_MODEL / 4;
        split_bf16<<<(n + 255) / 256, 256>>>(pAO, paoh, paol, n);
    }
    gemm_mma<<<dim3(D_MODEL / 128, NROWS / 128), 256, GEMM_SMEM_BYTES>>>(
        paoh, paol, pWoh, pWol, out, NROWS, D_MODEL, D_MODEL);
}

// round 7
// speedup vs baseline: 3.2142x; 1.1419x over previous
#include <cuda_runtime.h>
#include <cuda_bf16.h>
#include <stdint.h>
#include <math.h>

#define D_MODEL 2048
#define DKV     512
#define LSEQ    2048
#define BATCH   2
#define NROWS   (BATCH * LSEQ)   // 4096
#define QBLKS   (LSEQ / 128)     // 16
#define KBLKS   (LSEQ / 64)      // 32

typedef __nv_bfloat16 bf16;

// -------- scratch (no allocation allowed; device globals) --------
__device__ int  g_active[QBLKS * KBLKS];
__device__ int  g_zero[QBLKS * KBLKS];

__device__ bf16 g_xh [(size_t)NROWS * D_MODEL];
__device__ bf16 g_xl [(size_t)NROWS * D_MODEL];
__device__ bf16 g_Wqh[(size_t)D_MODEL * D_MODEL];
__device__ bf16 g_Wql[(size_t)D_MODEL * D_MODEL];
__device__ bf16 g_Wkh[(size_t)DKV * D_MODEL];
__device__ bf16 g_Wkl[(size_t)DKV * D_MODEL];
__device__ bf16 g_Wvh[(size_t)DKV * D_MODEL];
__device__ bf16 g_Wvl[(size_t)DKV * D_MODEL];
__device__ bf16 g_Woh[(size_t)D_MODEL * D_MODEL];
__device__ bf16 g_Wol[(size_t)D_MODEL * D_MODEL];
__device__ bf16 g_aoh[(size_t)NROWS * D_MODEL];
__device__ bf16 g_aol[(size_t)NROWS * D_MODEL];

// bf16 hi/lo of rope'd Q, K and of V (written by fused gemm epilogues)
__device__ bf16 g_Qh[(size_t)NROWS * D_MODEL];
__device__ bf16 g_Ql[(size_t)NROWS * D_MODEL];
__device__ bf16 g_Kh[(size_t)NROWS * DKV];
__device__ bf16 g_Kl[(size_t)NROWS * DKV];
__device__ bf16 g_Vh[(size_t)NROWS * DKV];
__device__ bf16 g_Vl[(size_t)NROWS * DKV];

// =================================================================
// PTX helpers (sm_80+ subset: mma.sync / ldmatrix / cp.async)
// =================================================================
__device__ __forceinline__ uint32_t smem_u32(const void* p) {
    uint32_t a;
    asm("{ .reg .u64 t; cvta.to.shared.u64 t, %1; cvt.u32.u64 %0, t; }" : "=r"(a) : "l"(p));
    return a;
}

__device__ __forceinline__ void cp16(uint32_t dst, const void* src) {
    asm volatile("cp.async.cg.shared.global [%0], [%1], 16;" :: "r"(dst), "l"(src) : "memory");
}
__device__ __forceinline__ void cp_commit() {
    asm volatile("cp.async.commit_group;" ::: "memory");
}
template <int N>
__device__ __forceinline__ void cp_wait() {
    asm volatile("cp.async.wait_group %0;" :: "n"(N) : "memory");
}

__device__ __forceinline__ void ldsm_x4(uint32_t* r, uint32_t addr) {
    asm volatile("ldmatrix.sync.aligned.m8n8.x4.shared.b16 {%0,%1,%2,%3}, [%4];"
                 : "=r"(r[0]), "=r"(r[1]), "=r"(r[2]), "=r"(r[3]) : "r"(addr));
}
__device__ __forceinline__ void ldsm_x4_t(uint32_t* r, uint32_t addr) {
    asm volatile("ldmatrix.sync.aligned.m8n8.x4.trans.shared.b16 {%0,%1,%2,%3}, [%4];"
                 : "=r"(r[0]), "=r"(r[1]), "=r"(r[2]), "=r"(r[3]) : "r"(addr));
}

__device__ __forceinline__ void mma_bf16(float* c, const uint32_t* a, const uint32_t* b) {
    asm volatile(
        "mma.sync.aligned.m16n8k16.row.col.f32.bf16.bf16.f32 "
        "{%0,%1,%2,%3}, {%4,%5,%6,%7}, {%8,%9}, {%0,%1,%2,%3};"
        : "+f"(c[0]), "+f"(c[1]), "+f"(c[2]), "+f"(c[3])
        : "r"(a[0]), "r"(a[1]), "r"(a[2]), "r"(a[3]), "r"(b[0]), "r"(b[1]));
}

__device__ __forceinline__ uint32_t pack_bf16x2(float lo, float hi) {
    uint32_t r;
    asm("cvt.rn.bf16x2.f32 %0, %1, %2;" : "=r"(r) : "f"(hi), "f"(lo));
    return r;
}
__device__ __forceinline__ float bf16lo_f(uint32_t r) { return __uint_as_float(r << 16); }
__device__ __forceinline__ float bf16hi_f(uint32_t r) { return __uint_as_float(r & 0xffff0000u); }

// split-store a pair of fp32 as (hi,lo) bf16 pairs at element index idx (even)
__device__ __forceinline__ void split_store2(bf16* __restrict__ H, bf16* __restrict__ L,
                                             size_t idx, float v0, float v1) {
    uint32_t h = pack_bf16x2(v0, v1);
    uint32_t l = pack_bf16x2(v0 - bf16lo_f(h), v1 - bf16hi_f(h));
    *(uint32_t*)(H + idx) = h;
    *(uint32_t*)(L + idx) = l;
}

// =================================================================
// split: fp32 -> bf16 hi + bf16 lo  (x = hi + lo)
// =================================================================
__global__ void split_bf16(const float* __restrict__ in,
                           bf16* __restrict__ hi, bf16* __restrict__ lo, int n4) {
    int i = blockIdx.x * blockDim.x + threadIdx.x;
    if (i >= n4) return;
    float4 x = ((const float4*)in)[i];
    bf16 h0 = __float2bfloat16(x.x), h1 = __float2bfloat16(x.y);
    bf16 h2 = __float2bfloat16(x.z), h3 = __float2bfloat16(x.w);
    bf16 l0 = __float2bfloat16(x.x - __bfloat162float(h0));
    bf16 l1 = __float2bfloat16(x.y - __bfloat162float(h1));
    bf16 l2 = __float2bfloat16(x.z - __bfloat162float(h2));
    bf16 l3 = __float2bfloat16(x.w - __bfloat162float(h3));
    __nv_bfloat162 hh0; hh0.x = h0; hh0.y = h1;
    __nv_bfloat162 hh1; hh1.x = h2; hh1.y = h3;
    __nv_bfloat162 ll0; ll0.x = l0; ll0.y = l1;
    __nv_bfloat162 ll1; ll1.x = l2; ll1.y = l3;
    ((__nv_bfloat162*)hi)[2 * i]     = hh0;
    ((__nv_bfloat162*)hi)[2 * i + 1] = hh1;
    ((__nv_bfloat162*)lo)[2 * i]     = ll0;
    ((__nv_bfloat162*)lo)[2 * i + 1] = ll1;
}

// =================================================================
// mask block stats: active = (blockmax > -1e8); zero = (blockmin > -1e8)
// =================================================================
__global__ void maskmax_kernel(const float* __restrict__ M,
                               int* __restrict__ act, int* __restrict__ zro) {
    __shared__ float rmax[256];
    __shared__ float rmin[256];
    const int qb = blockIdx.x, kb = blockIdx.y;
    const int t = threadIdx.x;
    float mx = -3.0e38f, mn = 3.0e38f;
    for (int e = t; e < 128 * 64 / 4; e += 256) {
        int r = e >> 4;
        int c = (e & 15) << 2;
        float4 v = *(const float4*)(M + (size_t)(qb * 128 + r) * LSEQ + kb * 64 + c);
        mx = fmaxf(mx, fmaxf(fmaxf(v.x, v.y), fmaxf(v.z, v.w)));
        mn = fminf(mn, fminf(fminf(v.x, v.y), fminf(v.z, v.w)));
    }
    rmax[t] = mx; rmin[t] = mn;
    __syncthreads();
    for (int s = 128; s > 0; s >>= 1) {
        if (t < s) {
            rmax[t] = fmaxf(rmax[t], rmax[t + s]);
            rmin[t] = fminf(rmin[t], rmin[t + s]);
        }
        __syncthreads();
    }
    if (t == 0) {
        act[qb * KBLKS + kb] = (rmax[0] > -1.0e8f) ? 1 : 0;
        zro[qb * KBLKS + kb] = (rmin[0] > -1.0e8f) ? 1 : 0;
    }
}

// =================================================================
// HMMA GEMM: C = (Ah+Al)[M,K] @ (Bh+Bl)[N,K]^T
// mode 0: fp32 out to Cf.  mode 1: split bf16 out (outH/outL).
// mode 2: fused RoPE (64-wide heads) + split bf16 out.
// =================================================================
#define GPAD        80
#define GTILE_BYTES (128 * GPAD)
#define GSTAGE      (4 * GTILE_BYTES)
#define GEMM_SMEM_BYTES (2 * GSTAGE)

__global__ void __launch_bounds__(256) gemm_mma(const bf16* __restrict__ Ah,
                                                const bf16* __restrict__ Al,
                                                const bf16* __restrict__ Bh,
                                                const bf16* __restrict__ Bl,
                                                float* __restrict__ Cf,
                                                bf16* __restrict__ outH,
                                                bf16* __restrict__ outL,
                                                int M, int N, int K, int mode) {
    extern __shared__ char dsm[];
    const uint32_t sb0 = smem_u32(dsm);

    const int t    = threadIdx.x;
    const int wid  = t >> 5;
    const int lane = t & 31;
    const int wm   = wid & 3;
    const int wn   = wid >> 2;
    const int m0   = blockIdx.y * 128;
    const int n0   = blockIdx.x * 128;

    const bf16* gbase[4] = { Ah + (size_t)m0 * K, Al + (size_t)m0 * K,
                             Bh + (size_t)n0 * K, Bl + (size_t)n0 * K };

    float acc[2][8][4];
#pragma unroll
    for (int i = 0; i < 2; i++)
#pragma unroll
        for (int j = 0; j < 8; j++)
#pragma unroll
            for (int c = 0; c < 4; c++) acc[i][j][c] = 0.f;

    const int niter = K >> 5;

    auto load_stage = [&](int it, int s) {
        const int kt = it << 5;
        const uint32_t sb = sb0 + s * GSTAGE;
#pragma unroll
        for (int u = 0; u < 8; u++) {
            int e   = t + 256 * u;
            int arr = e >> 9;
            int idx = e & 511;
            int row = idx >> 2;
            int ch  = idx & 3;
            cp16(sb + arr * GTILE_BYTES + row * GPAD + ch * 16,
                 gbase[arr] + (size_t)row * K + kt + ch * 8);
        }
        cp_commit();
    };

    load_stage(0, 0);
    if (niter > 1) load_stage(1, 1);
    cp_wait<1>();
    __syncthreads();

    const int r8  = lane & 7;
    const int sel = lane >> 3;
    const int aro = wm * 32 + ((sel & 1) << 3) + r8;
    const int aco = (sel >> 1) << 3;
    const int bro = wn * 64 + ((sel >> 1) << 3) + r8;
    const int bco = (sel & 1) << 3;

    for (int it = 0; it < niter; it++) {
        const int s = it & 1;
        const uint32_t sb = sb0 + s * GSTAGE;
#pragma unroll
        for (int ks = 0; ks < 2; ks++) {
            const int kof = ks << 4;
            uint32_t aH[2][4], aL[2][4];
#pragma unroll
            for (int mt = 0; mt < 2; mt++) {
                uint32_t aaddr = sb + (aro + mt * 16) * GPAD + (aco + kof) * 2;
                ldsm_x4(aH[mt], aaddr);
                ldsm_x4(aL[mt], aaddr + GTILE_BYTES);
            }
#pragma unroll
            for (int nt2 = 0; nt2 < 4; nt2++) {
                uint32_t baddr = sb + 2 * GTILE_BYTES
                               + (bro + nt2 * 16) * GPAD + (bco + kof) * 2;
                uint32_t bH[4], bL[4];
                ldsm_x4(bH, baddr);
                ldsm_x4(bL, baddr + GTILE_BYTES);
#pragma unroll
                for (int mt = 0; mt < 2; mt++) {
                    mma_bf16(acc[mt][2 * nt2],     aH[mt], bH);
                    mma_bf16(acc[mt][2 * nt2],     aH[mt], bL);
                    mma_bf16(acc[mt][2 * nt2],     aL[mt], bH);
                    mma_bf16(acc[mt][2 * nt2 + 1], aH[mt], bH + 2);
                    mma_bf16(acc[mt][2 * nt2 + 1], aH[mt], bL + 2);
                    mma_bf16(acc[mt][2 * nt2 + 1], aL[mt], bH + 2);
                }
            }
        }
        __syncthreads();
        if (it + 2 < niter) {
            load_stage(it + 2, s);
            cp_wait<1>();
        } else {
            cp_wait<0>();
        }
        __syncthreads();
    }

    // ---- epilogue ----
    const int erow = lane >> 2;
    const int ecol = (lane & 3) << 1;
    const int rowb = m0 + wm * 32 + erow;
    const int colb = n0 + wn * 64;

    if (mode == 0) {
#pragma unroll
        for (int mt = 0; mt < 2; mt++) {
#pragma unroll
            for (int nt = 0; nt < 8; nt++) {
                int row = rowb + mt * 16;
                int col = colb + nt * 8 + ecol;
                *(float2*)(Cf + (size_t)row * N + col)       = make_float2(acc[mt][nt][0], acc[mt][nt][1]);
                *(float2*)(Cf + (size_t)(row + 8) * N + col) = make_float2(acc[mt][nt][2], acc[mt][nt][3]);
            }
        }
    } else if (mode == 1) {
#pragma unroll
        for (int mt = 0; mt < 2; mt++) {
#pragma unroll
            for (int nt = 0; nt < 8; nt++) {
                int row = rowb + mt * 16;
                int col = colb + nt * 8 + ecol;
                split_store2(outH, outL, (size_t)row * N + col, acc[mt][nt][0], acc[mt][nt][1]);
                split_store2(outH, outL, (size_t)(row + 8) * N + col, acc[mt][nt][2], acc[mt][nt][3]);
            }
        }
    } else {
        // fused RoPE + split. Warp tile = one 64-wide head; pairs (nt, nt+4).
        float inv0[4], inv1[4];
#pragma unroll
        for (int nt = 0; nt < 4; nt++) {
            int j0 = nt * 8 + ecol;
            inv0[nt] = 1.0f / powf(10000.0f, (float)j0 * (1.0f / 32.0f));
            inv1[nt] = 1.0f / powf(10000.0f, (float)(j0 + 1) * (1.0f / 32.0f));
        }
#pragma unroll
        for (int mt = 0; mt < 2; mt++) {
#pragma unroll
            for (int half = 0; half < 2; half++) {
                int row = rowb + mt * 16 + 8 * half;
                int l   = row & (LSEQ - 1);
#pragma unroll
                for (int nt = 0; nt < 4; nt++) {
                    float s0, c0, s1, c1;
                    sincosf((float)l * inv0[nt], &s0, &c0);
                    sincosf((float)l * inv1[nt], &s1, &c1);
                    float x1a = acc[mt][nt][2 * half],     x1b = acc[mt][nt][2 * half + 1];
                    float x2a = acc[mt][nt + 4][2 * half], x2b = acc[mt][nt + 4][2 * half + 1];
                    float y1a = x1a * c0 - x2a * s0;
                    float y1b = x1b * c1 - x2b * s1;
                    float y2a = x2a * c0 + x1a * s0;
                    float y2b = x2b * c1 + x1b * s1;
                    int col = colb + nt * 8 + ecol;
                    split_store2(outH, outL, (size_t)row * N + col,            y1a, y1b);
                    split_store2(outH, outL, (size_t)row * N + col + 32,       y2a, y2b);
                }
            }
        }
    }
}

// =================================================================
// HMMA flash attention, bf16-split, register softmax.
// Emits bf16 hi/lo output directly. CTA = 128 q-rows x one (b,h).
// =================================================================
#define VPITCH     144
#define ATILE      (64 * VPITCH)
#define ASTAGE     (4 * ATILE)
#define ATTN_SMEM  (2 * ASTAGE + 256)

__global__ void __launch_bounds__(256) attn_mma(const bf16* __restrict__ Qhp,
                                                const bf16* __restrict__ Qlp,
                                                const bf16* __restrict__ Khp,
                                                const bf16* __restrict__ Klp,
                                                const bf16* __restrict__ Vhp,
                                                const bf16* __restrict__ Vlp,
                                                const float* __restrict__ Mg,
                                                const int* __restrict__ act,
                                                const int* __restrict__ zro,
                                                bf16* __restrict__ OH,
                                                bf16* __restrict__ OL) {
    extern __shared__ char sm8[];
    int* slist = (int*)(sm8 + 2 * ASTAGE);
    const uint32_t sb0 = smem_u32(sm8);

    const int t    = threadIdx.x;
    const int lane = t & 31;
    const int w    = t >> 5;
    const int qb   = blockIdx.x, q0 = qb * 128;
    const int h    = blockIdx.y, b = blockIdx.z, hk = h >> 2;

    if (t == 0) {
        int n = 0;
        for (int kb = 0; kb < KBLKS; kb++)
            if (act[qb * KBLKS + kb])
                slist[n++] = (kb << 1) | zro[qb * KBLKS + kb];
        slist[40] = n;
    }

    const bf16* qgh = Qhp + (size_t)(b * LSEQ + q0) * D_MODEL + h * 64;
    const bf16* qgl = Qlp + (size_t)(b * LSEQ + q0) * D_MODEL + h * 64;
#pragma unroll
    for (int u = 0; u < 4; u++) {
        int e = t + 256 * u;
        int row = e >> 3, ch = e & 7;
        cp16(sb0 + row * VPITCH + ch * 16,             qgh + (size_t)row * D_MODEL + ch * 8);
        cp16(sb0 + 2 * ATILE + row * VPITCH + ch * 16, qgl + (size_t)row * D_MODEL + ch * 8);
    }
    cp_commit();
    cp_wait<0>();
    __syncthreads();

    const int r8  = lane & 7;
    const int sel = lane >> 3;
    const int gr  = lane >> 2;
    const int gc2 = (lane & 3) << 1;

    uint32_t aH[4][4], aL[4][4];
    {
        const int aro = w * 16 + ((sel & 1) << 3) + r8;
        const int aco = (sel >> 1) << 3;
#pragma unroll
        for (int ks = 0; ks < 4; ks++) {
            uint32_t ad = sb0 + aro * VPITCH + (aco + ks * 16) * 2;
            ldsm_x4(aH[ks], ad);
            ldsm_x4(aL[ks], ad + 2 * ATILE);
        }
    }
    __syncthreads();

    const int nact = slist[40];

    const bf16* kbase_h = Khp + (size_t)(b * LSEQ) * DKV + hk * 64;
    const bf16* kbase_l = Klp + (size_t)(b * LSEQ) * DKV + hk * 64;
    const bf16* vbase_h = Vhp + (size_t)(b * LSEQ) * DKV + hk * 64;
    const bf16* vbase_l = Vlp + (size_t)(b * LSEQ) * DKV + hk * 64;

    auto stage = [&](int i, int s) {
        const int k0 = (slist[i] >> 1) * 64;
        const uint32_t sb = sb0 + s * ASTAGE;
        const bf16* bases[4] = { kbase_h + (size_t)k0 * DKV, kbase_l + (size_t)k0 * DKV,
                                 vbase_h + (size_t)k0 * DKV, vbase_l + (size_t)k0 * DKV };
#pragma unroll
        for (int u = 0; u < 8; u++) {
            int e   = t + 256 * u;
            int arr = e >> 9;
            int idx = e & 511;
            int row = idx >> 3, ch = idx & 7;
            cp16(sb + arr * ATILE + row * VPITCH + ch * 16,
                 bases[arr] + (size_t)row * DKV + ch * 8);
        }
        cp_commit();
    };

    float o[8][4];
#pragma unroll
    for (int j = 0; j < 8; j++)
#pragma unroll
        for (int c = 0; c < 4; c++) o[j][c] = 0.f;
    float m0r = -1.0e30f, m1r = -1.0e30f, l0r = 0.f, l1r = 0.f;

    stage(0, 0);
    if (nact > 1) stage(1, 1);

    const float* mrowb = Mg + (size_t)(q0 + w * 16 + gr) * LSEQ + gc2;

    for (int i = 0; i < nact; i++) {
        const int s  = i & 1;
        const int kb2 = slist[i];
        const int k0 = (kb2 >> 1) * 64;
        const int zf = kb2 & 1;
        const uint32_t sb  = sb0 + s * ASTAGE;

        if (i + 1 < nact) cp_wait<1>(); else cp_wait<0>();
        __syncthreads();

        // ---- S = Q K^T (split, 3 products) ----
        float sfr[8][4];
#pragma unroll
        for (int j = 0; j < 8; j++)
#pragma unroll
            for (int c = 0; c < 4; c++) sfr[j][c] = 0.f;
#pragma unroll
        for (int ks = 0; ks < 4; ks++) {
#pragma unroll
            for (int nt2 = 0; nt2 < 4; nt2++) {
                uint32_t kaddr = sb + (nt2 * 16 + ((sel >> 1) << 3) + r8) * VPITCH
                               + (ks * 16 + ((sel & 1) << 3)) * 2;
                uint32_t bH[4], bL[4];
                ldsm_x4(bH, kaddr);
                ldsm_x4(bL, kaddr + ATILE);
                mma_bf16(sfr[2 * nt2],     aH[ks], bH);
                mma_bf16(sfr[2 * nt2],     aH[ks], bL);
                mma_bf16(sfr[2 * nt2],     aL[ks], bH);
                mma_bf16(sfr[2 * nt2 + 1], aH[ks], bH + 2);
                mma_bf16(sfr[2 * nt2 + 1], aH[ks], bL + 2);
                mma_bf16(sfr[2 * nt2 + 1], aL[ks], bH + 2);
            }
        }

        // ---- scale (+ mask if not all-zero block) + register softmax ----
        float mx0 = -1.0e30f, mx1 = -1.0e30f;
        if (zf) {
#pragma unroll
            for (int j = 0; j < 8; j++) {
                sfr[j][0] *= 0.125f; sfr[j][1] *= 0.125f;
                sfr[j][2] *= 0.125f; sfr[j][3] *= 0.125f;
                mx0 = fmaxf(mx0, fmaxf(sfr[j][0], sfr[j][1]));
                mx1 = fmaxf(mx1, fmaxf(sfr[j][2], sfr[j][3]));
            }
        } else {
            const float* m0p = mrowb + k0;
            const float* m1p = m0p + 8 * LSEQ;
#pragma unroll
            for (int j = 0; j < 8; j++) {
                float2 u0 = *(const float2*)(m0p + 8 * j);
                float2 u1 = *(const float2*)(m1p + 8 * j);
                sfr[j][0] = fmaf(sfr[j][0], 0.125f, u0.x);
                sfr[j][1] = fmaf(sfr[j][1], 0.125f, u0.y);
                sfr[j][2] = fmaf(sfr[j][2], 0.125f, u1.x);
                sfr[j][3] = fmaf(sfr[j][3], 0.125f, u1.y);
                mx0 = fmaxf(mx0, fmaxf(sfr[j][0], sfr[j][1]));
                mx1 = fmaxf(mx1, fmaxf(sfr[j][2], sfr[j][3]));
            }
        }
        mx0 = fmaxf(mx0, __shfl_xor_sync(0xffffffffu, mx0, 1));
        mx0 = fmaxf(mx0, __shfl_xor_sync(0xffffffffu, mx0, 2));
        mx1 = fmaxf(mx1, __shfl_xor_sync(0xffffffffu, mx1, 1));
        mx1 = fmaxf(mx1, __shfl_xor_sync(0xffffffffu, mx1, 2));

        float mn0 = fmaxf(m0r, mx0), mn1 = fmaxf(m1r, mx1);
        float sc0 = __expf(m0r - mn0), sc1 = __expf(m1r - mn1);
        m0r = mn0; m1r = mn1;

        uint32_t paH[4][4], paL[4][4];
        float sum0 = 0.f, sum1 = 0.f;
#pragma unroll
        for (int j = 0; j < 8; j++) {
            float p0 = __expf(sfr[j][0] - mn0);
            float p1 = __expf(sfr[j][1] - mn0);
            float p2 = __expf(sfr[j][2] - mn1);
            float p3 = __expf(sfr[j][3] - mn1);
            sum0 += p0 + p1;
            sum1 += p2 + p3;
            uint32_t h01 = pack_bf16x2(p0, p1);
            uint32_t h23 = pack_bf16x2(p2, p3);
            uint32_t lo01 = pack_bf16x2(p0 - bf16lo_f(h01), p1 - bf16hi_f(h01));
            uint32_t lo23 = pack_bf16x2(p2 - bf16lo_f(h23), p3 - bf16hi_f(h23));
            int ks = j >> 1;
            int sl = (j & 1) << 1;
            paH[ks][sl]     = h01;
            paH[ks][sl + 1] = h23;
            paL[ks][sl]     = lo01;
            paL[ks][sl + 1] = lo23;
        }
        sum0 += __shfl_xor_sync(0xffffffffu, sum0, 1);
        sum0 += __shfl_xor_sync(0xffffffffu, sum0, 2);
        sum1 += __shfl_xor_sync(0xffffffffu, sum1, 1);
        sum1 += __shfl_xor_sync(0xffffffffu, sum1, 2);
        l0r = l0r * sc0 + sum0;
        l1r = l1r * sc1 + sum1;
#pragma unroll
        for (int j = 0; j < 8; j++) {
            o[j][0] *= sc0; o[j][1] *= sc0;
            o[j][2] *= sc1; o[j][3] *= sc1;
        }

        // ---- O += P V (split, 3 products); V via ldmatrix.trans ----
        const uint32_t sv = sb + 2 * ATILE;
#pragma unroll
        for (int ks = 0; ks < 4; ks++) {
#pragma unroll
            for (int nt2 = 0; nt2 < 4; nt2++) {
                uint32_t vaddr = sv + (ks * 16 + ((sel & 1) << 3) + r8) * VPITCH
                               + (nt2 * 16 + ((sel >> 1) << 3)) * 2;
                uint32_t vH[4], vL[4];
                ldsm_x4_t(vH, vaddr);
                ldsm_x4_t(vL, vaddr + ATILE);
                mma_bf16(o[2 * nt2],     paH[ks], vH);
                mma_bf16(o[2 * nt2],     paH[ks], vL);
                mma_bf16(o[2 * nt2],     paL[ks], vH);
                mma_bf16(o[2 * nt2 + 1], paH[ks], vH + 2);
                mma_bf16(o[2 * nt2 + 1], paH[ks], vL + 2);
                mma_bf16(o[2 * nt2 + 1], paL[ks], vH + 2);
            }
        }
        __syncthreads();
        if (i + 2 < nact) stage(i + 2, s);
    }

    // ---- normalize + split-store ----
    float inv0 = 1.0f / l0r, inv1 = 1.0f / l1r;
    const size_t r0 = (size_t)(b * LSEQ + q0 + w * 16 + gr) * D_MODEL + h * 64 + gc2;
    const size_t r1 = r0 + (size_t)8 * D_MODEL;
#pragma unroll
    for (int j = 0; j < 8; j++) {
        split_store2(OH, OL, r0 + 8 * j, o[j][0] * inv0, o[j][1] * inv0);
        split_store2(OH, OL, r1 + 8 * j, o[j][2] * inv1, o[j][3] * inv1);
    }
}

// =================================================================
// launch
// =================================================================
extern "C" void kernel_launch(void* const* d_in, const int* in_sizes, int n_in,
                              void* d_out, int out_size) {
    const float* x    = (const float*)d_in[0];
    const float* Wq   = (const float*)d_in[1];
    const float* Wk   = (const float*)d_in[2];
    const float* Wv   = (const float*)d_in[3];
    const float* Wo   = (const float*)d_in[4];
    const float* mask = (const float*)d_in[5];
    float* out = (float*)d_out;

    int *pact, *pzro;
    bf16 *pxh, *pxl, *pWqh, *pWql, *pWkh, *pWkl, *pWvh, *pWvl, *pWoh, *pWol, *paoh, *paol;
    bf16 *pQh, *pQl, *pKh, *pKl, *pVh, *pVl;
    cudaGetSymbolAddress((void**)&pact, g_active);
    cudaGetSymbolAddress((void**)&pzro, g_zero);
    cudaGetSymbolAddress((void**)&pxh, g_xh);   cudaGetSymbolAddress((void**)&pxl, g_xl);
    cudaGetSymbolAddress((void**)&pWqh, g_Wqh); cudaGetSymbolAddress((void**)&pWql, g_Wql);
    cudaGetSymbolAddress((void**)&pWkh, g_Wkh); cudaGetSymbolAddress((void**)&pWkl, g_Wkl);
    cudaGetSymbolAddress((void**)&pWvh, g_Wvh); cudaGetSymbolAddress((void**)&pWvl, g_Wvl);
    cudaGetSymbolAddress((void**)&pWoh, g_Woh); cudaGetSymbolAddress((void**)&pWol, g_Wol);
    cudaGetSymbolAddress((void**)&paoh, g_aoh); cudaGetSymbolAddress((void**)&paol, g_aol);
    cudaGetSymbolAddress((void**)&pQh, g_Qh);   cudaGetSymbolAddress((void**)&pQl, g_Ql);
    cudaGetSymbolAddress((void**)&pKh, g_Kh);   cudaGetSymbolAddress((void**)&pKl, g_Kl);
    cudaGetSymbolAddress((void**)&pVh, g_Vh);   cudaGetSymbolAddress((void**)&pVl, g_Vl);

    cudaFuncSetAttribute(attn_mma, cudaFuncAttributeMaxDynamicSharedMemorySize, ATTN_SMEM);
    cudaFuncSetAttribute(gemm_mma, cudaFuncAttributeMaxDynamicSharedMemorySize, GEMM_SMEM_BYTES);

    int n;
    // 1: mask block stats
    maskmax_kernel<<<dim3(QBLKS, KBLKS), 256>>>(mask, pact, pzro);
    // 2-3: split x, Wq
    n = NROWS * D_MODEL / 4;   split_bf16<<<(n + 255) / 256, 256>>>(x,  pxh,  pxl,  n);
    n = D_MODEL * D_MODEL / 4; split_bf16<<<(n + 255) / 256, 256>>>(Wq, pWqh, pWql, n);
    // 4: Q projection + fused RoPE + split
    gemm_mma<<<dim3(D_MODEL / 128, NROWS / 128), 256, GEMM_SMEM_BYTES>>>(
        pxh, pxl, pWqh, pWql, nullptr, pQh, pQl, NROWS, D_MODEL, D_MODEL, 2);
    // 5: split Wk
    n = DKV * D_MODEL / 4;     split_bf16<<<(n + 255) / 256, 256>>>(Wk, pWkh, pWkl, n);
    // 6: K projection + fused RoPE + split   (profiler target)
    gemm_mma<<<dim3(DKV / 128, NROWS / 128), 256, GEMM_SMEM_BYTES>>>(
        pxh, pxl, pWkh, pWkl, nullptr, pKh, pKl, NROWS, DKV, D_MODEL, 2);
    // 7: split Wv
    n = DKV * D_MODEL / 4;     split_bf16<<<(n + 255) / 256, 256>>>(Wv, pWvh, pWvl, n);
    // 8: V projection + split
    gemm_mma<<<dim3(DKV / 128, NROWS / 128), 256, GEMM_SMEM_BYTES>>>(
        pxh, pxl, pWvh, pWvl, nullptr, pVh, pVl, NROWS, DKV, D_MODEL, 1);
    // 9: attention (emits bf16 hi/lo)
    attn_mma<<<dim3(QBLKS, 32, BATCH), 256, ATTN_SMEM>>>(
        pQh, pQl, pKh, pKl, pVh, pVl, mask, pact, pzro, paoh, paol);
    // 10: split Wo
    n = D_MODEL * D_MODEL / 4; split_bf16<<<(n + 255) / 256, 256>>>(Wo, pWoh, pWol, n);
    // 11: O projection -> fp32 out
    gemm_mma<<<dim3(D_MODEL / 128, NROWS / 128), 256, GEMM_SMEM_BYTES>>>(
        paoh, paol, pWoh, pWol, out, nullptr, nullptr, NROWS, D_MODEL, D_MODEL, 0);
}

// round 8
// speedup vs baseline: 3.4452x; 1.0719x over previous
#include <cuda_runtime.h>
#include <cuda_bf16.h>
#include <stdint.h>
#include <math.h>

#define D_MODEL 2048
#define DKV     512
#define LSEQ    2048
#define BATCH   2
#define NROWS   (BATCH * LSEQ)   // 4096
#define QBLKS   (LSEQ / 128)     // 16
#define KBLKS   (LSEQ / 64)      // 32

typedef __nv_bfloat16 bf16;

// -------- scratch (no allocation allowed; device globals) --------
__device__ int  g_active[QBLKS * KBLKS];
__device__ int  g_zero[QBLKS * KBLKS];

__device__ bf16 g_xh [(size_t)NROWS * D_MODEL];
__device__ bf16 g_xl [(size_t)NROWS * D_MODEL];
__device__ bf16 g_Wqh[(size_t)D_MODEL * D_MODEL];
__device__ bf16 g_Wql[(size_t)D_MODEL * D_MODEL];
__device__ bf16 g_Wkh[(size_t)DKV * D_MODEL];
__device__ bf16 g_Wkl[(size_t)DKV * D_MODEL];
__device__ bf16 g_Wvh[(size_t)DKV * D_MODEL];
__device__ bf16 g_Wvl[(size_t)DKV * D_MODEL];
__device__ bf16 g_Woh[(size_t)D_MODEL * D_MODEL];
__device__ bf16 g_Wol[(size_t)D_MODEL * D_MODEL];
__device__ bf16 g_aoh[(size_t)NROWS * D_MODEL];
__device__ bf16 g_aol[(size_t)NROWS * D_MODEL];

__device__ bf16 g_Qh[(size_t)NROWS * D_MODEL];
__device__ bf16 g_Ql[(size_t)NROWS * D_MODEL];
__device__ bf16 g_Kh[(size_t)NROWS * DKV];
__device__ bf16 g_Kl[(size_t)NROWS * DKV];
__device__ bf16 g_Vh[(size_t)NROWS * DKV];
__device__ bf16 g_Vl[(size_t)NROWS * DKV];

// =================================================================
// PTX helpers
// =================================================================
__device__ __forceinline__ uint32_t smem_u32(const void* p) {
    uint32_t a;
    asm("{ .reg .u64 t; cvta.to.shared.u64 t, %1; cvt.u32.u64 %0, t; }" : "=r"(a) : "l"(p));
    return a;
}

__device__ __forceinline__ void cp16(uint32_t dst, const void* src) {
    asm volatile("cp.async.cg.shared.global [%0], [%1], 16;" :: "r"(dst), "l"(src) : "memory");
}
__device__ __forceinline__ void cp_commit() {
    asm volatile("cp.async.commit_group;" ::: "memory");
}
template <int N>
__device__ __forceinline__ void cp_wait() {
    asm volatile("cp.async.wait_group %0;" :: "n"(N) : "memory");
}

__device__ __forceinline__ void ldsm_x4(uint32_t* r, uint32_t addr) {
    asm volatile("ldmatrix.sync.aligned.m8n8.x4.shared.b16 {%0,%1,%2,%3}, [%4];"
                 : "=r"(r[0]), "=r"(r[1]), "=r"(r[2]), "=r"(r[3]) : "r"(addr));
}
__device__ __forceinline__ void ldsm_x4_t(uint32_t* r, uint32_t addr) {
    asm volatile("ldmatrix.sync.aligned.m8n8.x4.trans.shared.b16 {%0,%1,%2,%3}, [%4];"
                 : "=r"(r[0]), "=r"(r[1]), "=r"(r[2]), "=r"(r[3]) : "r"(addr));
}

__device__ __forceinline__ void mma_bf16(float* c, const uint32_t* a, const uint32_t* b) {
    asm volatile(
        "mma.sync.aligned.m16n8k16.row.col.f32.bf16.bf16.f32 "
        "{%0,%1,%2,%3}, {%4,%5,%6,%7}, {%8,%9}, {%0,%1,%2,%3};"
        : "+f"(c[0]), "+f"(c[1]), "+f"(c[2]), "+f"(c[3])
        : "r"(a[0]), "r"(a[1]), "r"(a[2]), "r"(a[3]), "r"(b[0]), "r"(b[1]));
}

__device__ __forceinline__ uint32_t pack_bf16x2(float lo, float hi) {
    uint32_t r;
    asm("cvt.rn.bf16x2.f32 %0, %1, %2;" : "=r"(r) : "f"(hi), "f"(lo));
    return r;
}
__device__ __forceinline__ float bf16lo_f(uint32_t r) { return __uint_as_float(r << 16); }
__device__ __forceinline__ float bf16hi_f(uint32_t r) { return __uint_as_float(r & 0xffff0000u); }

__device__ __forceinline__ void split_store2(bf16* __restrict__ H, bf16* __restrict__ L,
                                             size_t idx, float v0, float v1) {
    uint32_t h = pack_bf16x2(v0, v1);
    uint32_t l = pack_bf16x2(v0 - bf16lo_f(h), v1 - bf16hi_f(h));
    *(uint32_t*)(H + idx) = h;
    *(uint32_t*)(L + idx) = l;
}

// =================================================================
// split: fp32 -> bf16 hi + bf16 lo
// =================================================================
__global__ void split_bf16(const float* __restrict__ in,
                           bf16* __restrict__ hi, bf16* __restrict__ lo, int n4) {
    int i = blockIdx.x * blockDim.x + threadIdx.x;
    if (i >= n4) return;
    float4 x = ((const float4*)in)[i];
    bf16 h0 = __float2bfloat16(x.x), h1 = __float2bfloat16(x.y);
    bf16 h2 = __float2bfloat16(x.z), h3 = __float2bfloat16(x.w);
    bf16 l0 = __float2bfloat16(x.x - __bfloat162float(h0));
    bf16 l1 = __float2bfloat16(x.y - __bfloat162float(h1));
    bf16 l2 = __float2bfloat16(x.z - __bfloat162float(h2));
    bf16 l3 = __float2bfloat16(x.w - __bfloat162float(h3));
    __nv_bfloat162 hh0; hh0.x = h0; hh0.y = h1;
    __nv_bfloat162 hh1; hh1.x = h2; hh1.y = h3;
    __nv_bfloat162 ll0; ll0.x = l0; ll0.y = l1;
    __nv_bfloat162 ll1; ll1.x = l2; ll1.y = l3;
    ((__nv_bfloat162*)hi)[2 * i]     = hh0;
    ((__nv_bfloat162*)hi)[2 * i + 1] = hh1;
    ((__nv_bfloat162*)lo)[2 * i]     = ll0;
    ((__nv_bfloat162*)lo)[2 * i + 1] = ll1;
}

// =================================================================
// mask block stats
// =================================================================
__global__ void maskmax_kernel(const float* __restrict__ M,
                               int* __restrict__ act, int* __restrict__ zro) {
    __shared__ float rmax[256];
    __shared__ float rmin[256];
    const int qb = blockIdx.x, kb = blockIdx.y;
    const int t = threadIdx.x;
    float mx = -3.0e38f, mn = 3.0e38f;
    for (int e = t; e < 128 * 64 / 4; e += 256) {
        int r = e >> 4;
        int c = (e & 15) << 2;
        float4 v = *(const float4*)(M + (size_t)(qb * 128 + r) * LSEQ + kb * 64 + c);
        mx = fmaxf(mx, fmaxf(fmaxf(v.x, v.y), fmaxf(v.z, v.w)));
        mn = fminf(mn, fminf(fminf(v.x, v.y), fminf(v.z, v.w)));
    }
    rmax[t] = mx; rmin[t] = mn;
    __syncthreads();
    for (int s = 128; s > 0; s >>= 1) {
        if (t < s) {
            rmax[t] = fmaxf(rmax[t], rmax[t + s]);
            rmin[t] = fminf(rmin[t], rmin[t + s]);
        }
        __syncthreads();
    }
    if (t == 0) {
        act[qb * KBLKS + kb] = (rmax[0] > -1.0e8f) ? 1 : 0;
        zro[qb * KBLKS + kb] = (rmin[0] > -1.0e8f) ? 1 : 0;
    }
}

// =================================================================
// HMMA GEMM. mode 0: fp32 out. mode 1: split out. mode 2: rope+split.
// mode 3: z-select fused KV (z0: B/outA rope; z1: B2/out2 plain).
// MMA order is product-major (acc reuse distance 4) to break
// accumulator dependency chains.
// =================================================================
#define GPAD        80
#define GTILE_BYTES (128 * GPAD)
#define GSTAGE      (4 * GTILE_BYTES)
#define GEMM_SMEM_BYTES (2 * GSTAGE)

__global__ void __launch_bounds__(256) gemm_mma(const bf16* __restrict__ Ah,
                                                const bf16* __restrict__ Al,
                                                const bf16* __restrict__ Bh_,
                                                const bf16* __restrict__ Bl_,
                                                const bf16* __restrict__ Bh2,
                                                const bf16* __restrict__ Bl2,
                                                float* __restrict__ Cf,
                                                bf16* __restrict__ oH_,
                                                bf16* __restrict__ oL_,
                                                bf16* __restrict__ oH2,
                                                bf16* __restrict__ oL2,
                                                int M, int N, int K, int mode) {
    extern __shared__ char dsm[];
    const uint32_t sb0 = smem_u32(dsm);

    const bf16* Bh = Bh_;
    const bf16* Bl = Bl_;
    bf16* outH = oH_;
    bf16* outL = oL_;
    int em = mode;
    if (mode == 3) {
        if (blockIdx.z == 0) { em = 2; }
        else { Bh = Bh2; Bl = Bl2; outH = oH2; outL = oL2; em = 1; }
    }

    const int t    = threadIdx.x;
    const int wid  = t >> 5;
    const int lane = t & 31;
    const int wm   = wid & 3;
    const int wn   = wid >> 2;
    const int m0   = blockIdx.y * 128;
    const int n0   = blockIdx.x * 128;

    const bf16* gbase[4] = { Ah + (size_t)m0 * K, Al + (size_t)m0 * K,
                             Bh + (size_t)n0 * K, Bl + (size_t)n0 * K };

    float acc[2][8][4];
#pragma unroll
    for (int i = 0; i < 2; i++)
#pragma unroll
        for (int j = 0; j < 8; j++)
#pragma unroll
            for (int c = 0; c < 4; c++) acc[i][j][c] = 0.f;

    const int niter = K >> 5;

    auto load_stage = [&](int it, int s) {
        const int kt = it << 5;
        const uint32_t sb = sb0 + s * GSTAGE;
#pragma unroll
        for (int u = 0; u < 8; u++) {
            int e   = t + 256 * u;
            int arr = e >> 9;
            int idx = e & 511;
            int row = idx >> 2;
            int ch  = idx & 3;
            cp16(sb + arr * GTILE_BYTES + row * GPAD + ch * 16,
                 gbase[arr] + (size_t)row * K + kt + ch * 8);
        }
        cp_commit();
    };

    load_stage(0, 0);
    if (niter > 1) load_stage(1, 1);
    cp_wait<1>();
    __syncthreads();

    const int r8  = lane & 7;
    const int sel = lane >> 3;
    const int aro = wm * 32 + ((sel & 1) << 3) + r8;
    const int aco = (sel >> 1) << 3;
    const int bro = wn * 64 + ((sel >> 1) << 3) + r8;
    const int bco = (sel & 1) << 3;

    for (int it = 0; it < niter; it++) {
        const int s = it & 1;
        const uint32_t sb = sb0 + s * GSTAGE;
#pragma unroll
        for (int ks = 0; ks < 2; ks++) {
            const int kof = ks << 4;
            uint32_t aH[2][4], aL[2][4];
#pragma unroll
            for (int mt = 0; mt < 2; mt++) {
                uint32_t aaddr = sb + (aro + mt * 16) * GPAD + (aco + kof) * 2;
                ldsm_x4(aH[mt], aaddr);
                ldsm_x4(aL[mt], aaddr + GTILE_BYTES);
            }
#pragma unroll
            for (int nt2 = 0; nt2 < 4; nt2++) {
                uint32_t baddr = sb + 2 * GTILE_BYTES
                               + (bro + nt2 * 16) * GPAD + (bco + kof) * 2;
                uint32_t bH[4], bL[4];
                ldsm_x4(bH, baddr);
                ldsm_x4(bL, baddr + GTILE_BYTES);
                float* a00 = acc[0][2 * nt2];
                float* a01 = acc[0][2 * nt2 + 1];
                float* a10 = acc[1][2 * nt2];
                float* a11 = acc[1][2 * nt2 + 1];
                // product-major: 4 independent accs between reuses
                mma_bf16(a00, aH[0], bH);
                mma_bf16(a01, aH[0], bH + 2);
                mma_bf16(a10, aH[1], bH);
                mma_bf16(a11, aH[1], bH + 2);
                mma_bf16(a00, aH[0], bL);
                mma_bf16(a01, aH[0], bL + 2);
                mma_bf16(a10, aH[1], bL);
                mma_bf16(a11, aH[1], bL + 2);
                mma_bf16(a00, aL[0], bH);
                mma_bf16(a01, aL[0], bH + 2);
                mma_bf16(a10, aL[1], bH);
                mma_bf16(a11, aL[1], bH + 2);
            }
        }
        __syncthreads();
        if (it + 2 < niter) {
            load_stage(it + 2, s);
            cp_wait<1>();
        } else {
            cp_wait<0>();
        }
        __syncthreads();
    }

    // ---- epilogue ----
    const int erow = lane >> 2;
    const int ecol = (lane & 3) << 1;
    const int rowb = m0 + wm * 32 + erow;
    const int colb = n0 + wn * 64;

    if (em == 0) {
#pragma unroll
        for (int mt = 0; mt < 2; mt++) {
#pragma unroll
            for (int nt = 0; nt < 8; nt++) {
                int row = rowb + mt * 16;
                int col = colb + nt * 8 + ecol;
                *(float2*)(Cf + (size_t)row * N + col)       = make_float2(acc[mt][nt][0], acc[mt][nt][1]);
                *(float2*)(Cf + (size_t)(row + 8) * N + col) = make_float2(acc[mt][nt][2], acc[mt][nt][3]);
            }
        }
    } else if (em == 1) {
#pragma unroll
        for (int mt = 0; mt < 2; mt++) {
#pragma unroll
            for (int nt = 0; nt < 8; nt++) {
                int row = rowb + mt * 16;
                int col = colb + nt * 8 + ecol;
                split_store2(outH, outL, (size_t)row * N + col, acc[mt][nt][0], acc[mt][nt][1]);
                split_store2(outH, outL, (size_t)(row + 8) * N + col, acc[mt][nt][2], acc[mt][nt][3]);
            }
        }
    } else {
        float inv0[4], inv1[4];
#pragma unroll
        for (int nt = 0; nt < 4; nt++) {
            int j0 = nt * 8 + ecol;
            inv0[nt] = 1.0f / powf(10000.0f, (float)j0 * (1.0f / 32.0f));
            inv1[nt] = 1.0f / powf(10000.0f, (float)(j0 + 1) * (1.0f / 32.0f));
        }
#pragma unroll
        for (int mt = 0; mt < 2; mt++) {
#pragma unroll
            for (int half = 0; half < 2; half++) {
                int row = rowb + mt * 16 + 8 * half;
                int l   = row & (LSEQ - 1);
#pragma unroll
                for (int nt = 0; nt < 4; nt++) {
                    float s0, c0, s1, c1;
                    sincosf((float)l * inv0[nt], &s0, &c0);
                    sincosf((float)l * inv1[nt], &s1, &c1);
                    float x1a = acc[mt][nt][2 * half],     x1b = acc[mt][nt][2 * half + 1];
                    float x2a = acc[mt][nt + 4][2 * half], x2b = acc[mt][nt + 4][2 * half + 1];
                    float y1a = x1a * c0 - x2a * s0;
                    float y1b = x1b * c1 - x2b * s1;
                    float y2a = x2a * c0 + x1a * s0;
                    float y2b = x2b * c1 + x1b * s1;
                    int col = colb + nt * 8 + ecol;
                    split_store2(outH, outL, (size_t)row * N + col,      y1a, y1b);
                    split_store2(outH, outL, (size_t)row * N + col + 32, y2a, y2b);
                }
            }
        }
    }
}

// =================================================================
// HMMA flash attention, bf16-split, register softmax, split output.
// =================================================================
#define VPITCH     144
#define ATILE      (64 * VPITCH)
#define ASTAGE     (4 * ATILE)
#define ATTN_SMEM  (2 * ASTAGE + 256)

__global__ void __launch_bounds__(256) attn_mma(const bf16* __restrict__ Qhp,
                                                const bf16* __restrict__ Qlp,
                                                const bf16* __restrict__ Khp,
                                                const bf16* __restrict__ Klp,
                                                const bf16* __restrict__ Vhp,
                                                const bf16* __restrict__ Vlp,
                                                const float* __restrict__ Mg,
                                                const int* __restrict__ act,
                                                const int* __restrict__ zro,
                                                bf16* __restrict__ OH,
                                                bf16* __restrict__ OL) {
    extern __shared__ char sm8[];
    int* slist = (int*)(sm8 + 2 * ASTAGE);
    const uint32_t sb0 = smem_u32(sm8);

    const int t    = threadIdx.x;
    const int lane = t & 31;
    const int w    = t >> 5;
    const int qb   = blockIdx.x, q0 = qb * 128;
    const int h    = blockIdx.y, b = blockIdx.z, hk = h >> 2;

    if (t == 0) {
        int n = 0;
        for (int kb = 0; kb < KBLKS; kb++)
            if (act[qb * KBLKS + kb])
                slist[n++] = (kb << 1) | zro[qb * KBLKS + kb];
        slist[40] = n;
    }

    const bf16* qgh = Qhp + (size_t)(b * LSEQ + q0) * D_MODEL + h * 64;
    const bf16* qgl = Qlp + (size_t)(b * LSEQ + q0) * D_MODEL + h * 64;
#pragma unroll
    for (int u = 0; u < 4; u++) {
        int e = t + 256 * u;
        int row = e >> 3, ch = e & 7;
        cp16(sb0 + row * VPITCH + ch * 16,             qgh + (size_t)row * D_MODEL + ch * 8);
        cp16(sb0 + 2 * ATILE + row * VPITCH + ch * 16, qgl + (size_t)row * D_MODEL + ch * 8);
    }
    cp_commit();
    cp_wait<0>();
    __syncthreads();

    const int r8  = lane & 7;
    const int sel = lane >> 3;
    const int gr  = lane >> 2;
    const int gc2 = (lane & 3) << 1;

    uint32_t aH[4][4], aL[4][4];
    {
        const int aro = w * 16 + ((sel & 1) << 3) + r8;
        const int aco = (sel >> 1) << 3;
#pragma unroll
        for (int ks = 0; ks < 4; ks++) {
            uint32_t ad = sb0 + aro * VPITCH + (aco + ks * 16) * 2;
            ldsm_x4(aH[ks], ad);
            ldsm_x4(aL[ks], ad + 2 * ATILE);
        }
    }
    __syncthreads();

    const int nact = slist[40];

    const bf16* kbase_h = Khp + (size_t)(b * LSEQ) * DKV + hk * 64;
    const bf16* kbase_l = Klp + (size_t)(b * LSEQ) * DKV + hk * 64;
    const bf16* vbase_h = Vhp + (size_t)(b * LSEQ) * DKV + hk * 64;
    const bf16* vbase_l = Vlp + (size_t)(b * LSEQ) * DKV + hk * 64;

    auto stage = [&](int i, int s) {
        const int k0 = (slist[i] >> 1) * 64;
        const uint32_t sb = sb0 + s * ASTAGE;
        const bf16* bases[4] = { kbase_h + (size_t)k0 * DKV, kbase_l + (size_t)k0 * DKV,
                                 vbase_h + (size_t)k0 * DKV, vbase_l + (size_t)k0 * DKV };
#pragma unroll
        for (int u = 0; u < 8; u++) {
            int e   = t + 256 * u;
            int arr = e >> 9;
            int idx = e & 511;
            int row = idx >> 3, ch = idx & 7;
            cp16(sb + arr * ATILE + row * VPITCH + ch * 16,
                 bases[arr] + (size_t)row * DKV + ch * 8);
        }
        cp_commit();
    };

    float o[8][4];
#pragma unroll
    for (int j = 0; j < 8; j++)
#pragma unroll
        for (int c = 0; c < 4; c++) o[j][c] = 0.f;
    float m0r = -1.0e30f, m1r = -1.0e30f, l0r = 0.f, l1r = 0.f;

    stage(0, 0);
    if (nact > 1) stage(1, 1);

    const float* mrowb = Mg + (size_t)(q0 + w * 16 + gr) * LSEQ + gc2;

    for (int i = 0; i < nact; i++) {
        const int s  = i & 1;
        const int kb2 = slist[i];
        const int k0 = (kb2 >> 1) * 64;
        const int zf = kb2 & 1;
        const uint32_t sb  = sb0 + s * ASTAGE;

        if (i + 1 < nact) cp_wait<1>(); else cp_wait<0>();
        __syncthreads();

        // ---- S = Q K^T (split, product-major order) ----
        float sfr[8][4];
#pragma unroll
        for (int j = 0; j < 8; j++)
#pragma unroll
            for (int c = 0; c < 4; c++) sfr[j][c] = 0.f;
#pragma unroll
        for (int ks = 0; ks < 4; ks++) {
#pragma unroll
            for (int nt2 = 0; nt2 < 4; nt2++) {
                uint32_t kaddr = sb + (nt2 * 16 + ((sel >> 1) << 3) + r8) * VPITCH
                               + (ks * 16 + ((sel & 1) << 3)) * 2;
                uint32_t bH[4], bL[4];
                ldsm_x4(bH, kaddr);
                ldsm_x4(bL, kaddr + ATILE);
                float* s0 = sfr[2 * nt2];
                float* s1 = sfr[2 * nt2 + 1];
                mma_bf16(s0, aH[ks], bH);
                mma_bf16(s1, aH[ks], bH + 2);
                mma_bf16(s0, aH[ks], bL);
                mma_bf16(s1, aH[ks], bL + 2);
                mma_bf16(s0, aL[ks], bH);
                mma_bf16(s1, aL[ks], bH + 2);
            }
        }

        // ---- scale (+ mask) + register softmax ----
        float mx0 = -1.0e30f, mx1 = -1.0e30f;
        if (zf) {
#pragma unroll
            for (int j = 0; j < 8; j++) {
                sfr[j][0] *= 0.125f; sfr[j][1] *= 0.125f;
                sfr[j][2] *= 0.125f; sfr[j][3] *= 0.125f;
                mx0 = fmaxf(mx0, fmaxf(sfr[j][0], sfr[j][1]));
                mx1 = fmaxf(mx1, fmaxf(sfr[j][2], sfr[j][3]));
            }
        } else {
            const float* m0p = mrowb + k0;
            const float* m1p = m0p + 8 * LSEQ;
#pragma unroll
            for (int j = 0; j < 8; j++) {
                float2 u0 = *(const float2*)(m0p + 8 * j);
                float2 u1 = *(const float2*)(m1p + 8 * j);
                sfr[j][0] = fmaf(sfr[j][0], 0.125f, u0.x);
                sfr[j][1] = fmaf(sfr[j][1], 0.125f, u0.y);
                sfr[j][2] = fmaf(sfr[j][2], 0.125f, u1.x);
                sfr[j][3] = fmaf(sfr[j][3], 0.125f, u1.y);
                mx0 = fmaxf(mx0, fmaxf(sfr[j][0], sfr[j][1]));
                mx1 = fmaxf(mx1, fmaxf(sfr[j][2], sfr[j][3]));
            }
        }
        mx0 = fmaxf(mx0, __shfl_xor_sync(0xffffffffu, mx0, 1));
        mx0 = fmaxf(mx0, __shfl_xor_sync(0xffffffffu, mx0, 2));
        mx1 = fmaxf(mx1, __shfl_xor_sync(0xffffffffu, mx1, 1));
        mx1 = fmaxf(mx1, __shfl_xor_sync(0xffffffffu, mx1, 2));

        float mn0 = fmaxf(m0r, mx0), mn1 = fmaxf(m1r, mx1);
        float sc0 = __expf(m0r - mn0), sc1 = __expf(m1r - mn1);
        m0r = mn0; m1r = mn1;

        uint32_t paH[4][4], paL[4][4];
        float sum0 = 0.f, sum1 = 0.f;
#pragma unroll
        for (int j = 0; j < 8; j++) {
            float p0 = __expf(sfr[j][0] - mn0);
            float p1 = __expf(sfr[j][1] - mn0);
            float p2 = __expf(sfr[j][2] - mn1);
            float p3 = __expf(sfr[j][3] - mn1);
            sum0 += p0 + p1;
            sum1 += p2 + p3;
            uint32_t h01 = pack_bf16x2(p0, p1);
            uint32_t h23 = pack_bf16x2(p2, p3);
            uint32_t lo01 = pack_bf16x2(p0 - bf16lo_f(h01), p1 - bf16hi_f(h01));
            uint32_t lo23 = pack_bf16x2(p2 - bf16lo_f(h23), p3 - bf16hi_f(h23));
            int ks = j >> 1;
            int sl = (j & 1) << 1;
            paH[ks][sl]     = h01;
            paH[ks][sl + 1] = h23;
            paL[ks][sl]     = lo01;
            paL[ks][sl + 1] = lo23;
        }
        sum0 += __shfl_xor_sync(0xffffffffu, sum0, 1);
        sum0 += __shfl_xor_sync(0xffffffffu, sum0, 2);
        sum1 += __shfl_xor_sync(0xffffffffu, sum1, 1);
        sum1 += __shfl_xor_sync(0xffffffffu, sum1, 2);
        l0r = l0r * sc0 + sum0;
        l1r = l1r * sc1 + sum1;
#pragma unroll
        for (int j = 0; j < 8; j++) {
            o[j][0] *= sc0; o[j][1] *= sc0;
            o[j][2] *= sc1; o[j][3] *= sc1;
        }

        // ---- O += P V (split, product-major order) ----
        const uint32_t sv = sb + 2 * ATILE;
#pragma unroll
        for (int ks = 0; ks < 4; ks++) {
#pragma unroll
            for (int nt2 = 0; nt2 < 4; nt2++) {
                uint32_t vaddr = sv + (ks * 16 + ((sel & 1) << 3) + r8) * VPITCH
                               + (nt2 * 16 + ((sel >> 1) << 3)) * 2;
                uint32_t vH[4], vL[4];
                ldsm_x4_t(vH, vaddr);
                ldsm_x4_t(vL, vaddr + ATILE);
                float* o0 = o[2 * nt2];
                float* o1 = o[2 * nt2 + 1];
                mma_bf16(o0, paH[ks], vH);
                mma_bf16(o1, paH[ks], vH + 2);
                mma_bf16(o0, paH[ks], vL);
                mma_bf16(o1, paH[ks], vL + 2);
                mma_bf16(o0, paL[ks], vH);
                mma_bf16(o1, paL[ks], vH + 2);
            }
        }
        __syncthreads();
        if (i + 2 < nact) stage(i + 2, s);
    }

    // ---- normalize + split-store ----
    float inv0 = 1.0f / l0r, inv1 = 1.0f / l1r;
    const size_t r0 = (size_t)(b * LSEQ + q0 + w * 16 + gr) * D_MODEL + h * 64 + gc2;
    const size_t r1 = r0 + (size_t)8 * D_MODEL;
#pragma unroll
    for (int j = 0; j < 8; j++) {
        split_store2(OH, OL, r0 + 8 * j, o[j][0] * inv0, o[j][1] * inv0);
        split_store2(OH, OL, r1 + 8 * j, o[j][2] * inv1, o[j][3] * inv1);
    }
}

// =================================================================
// launch
// =================================================================
extern "C" void kernel_launch(void* const* d_in, const int* in_sizes, int n_in,
                              void* d_out, int out_size) {
    const float* x    = (const float*)d_in[0];
    const float* Wq   = (const float*)d_in[1];
    const float* Wk   = (const float*)d_in[2];
    const float* Wv   = (const float*)d_in[3];
    const float* Wo   = (const float*)d_in[4];
    const float* mask = (const float*)d_in[5];
    float* out = (float*)d_out;

    int *pact, *pzro;
    bf16 *pxh, *pxl, *pWqh, *pWql, *pWkh, *pWkl, *pWvh, *pWvl, *pWoh, *pWol, *paoh, *paol;
    bf16 *pQh, *pQl, *pKh, *pKl, *pVh, *pVl;
    cudaGetSymbolAddress((void**)&pact, g_active);
    cudaGetSymbolAddress((void**)&pzro, g_zero);
    cudaGetSymbolAddress((void**)&pxh, g_xh);   cudaGetSymbolAddress((void**)&pxl, g_xl);
    cudaGetSymbolAddress((void**)&pWqh, g_Wqh); cudaGetSymbolAddress((void**)&pWql, g_Wql);
    cudaGetSymbolAddress((void**)&pWkh, g_Wkh); cudaGetSymbolAddress((void**)&pWkl, g_Wkl);
    cudaGetSymbolAddress((void**)&pWvh, g_Wvh); cudaGetSymbolAddress((void**)&pWvl, g_Wvl);
    cudaGetSymbolAddress((void**)&pWoh, g_Woh); cudaGetSymbolAddress((void**)&pWol, g_Wol);
    cudaGetSymbolAddress((void**)&paoh, g_aoh); cudaGetSymbolAddress((void**)&paol, g_aol);
    cudaGetSymbolAddress((void**)&pQh, g_Qh);   cudaGetSymbolAddress((void**)&pQl, g_Ql);
    cudaGetSymbolAddress((void**)&pKh, g_Kh);   cudaGetSymbolAddress((void**)&pKl, g_Kl);
    cudaGetSymbolAddress((void**)&pVh, g_Vh);   cudaGetSymbolAddress((void**)&pVl, g_Vl);

    cudaFuncSetAttribute(attn_mma, cudaFuncAttributeMaxDynamicSharedMemorySize, ATTN_SMEM);
    cudaFuncSetAttribute(gemm_mma, cudaFuncAttributeMaxDynamicSharedMemorySize, GEMM_SMEM_BYTES);

    int n;
    // mask block stats
    maskmax_kernel<<<dim3(QBLKS, KBLKS), 256>>>(mask, pact, pzro);
    // splits: x, Wq, Wk, Wv
    n = NROWS * D_MODEL / 4;   split_bf16<<<(n + 255) / 256, 256>>>(x,  pxh,  pxl,  n);
    n = D_MODEL * D_MODEL / 4; split_bf16<<<(n + 255) / 256, 256>>>(Wq, pWqh, pWql, n);
    n = DKV * D_MODEL / 4;     split_bf16<<<(n + 255) / 256, 256>>>(Wk, pWkh, pWkl, n);
    n = DKV * D_MODEL / 4;     split_bf16<<<(n + 255) / 256, 256>>>(Wv, pWvh, pWvl, n);
    // Q projection + fused RoPE + split
    gemm_mma<<<dim3(D_MODEL / 128, NROWS / 128), 256, GEMM_SMEM_BYTES>>>(
        pxh, pxl, pWqh, pWql, nullptr, nullptr, nullptr, pQh, pQl, nullptr, nullptr,
        NROWS, D_MODEL, D_MODEL, 2);
    // fused K (rope) + V projection, z-select
    gemm_mma<<<dim3(DKV / 128, NROWS / 128, 2), 256, GEMM_SMEM_BYTES>>>(
        pxh, pxl, pWkh, pWkl, pWvh, pWvl, nullptr, pKh, pKl, pVh, pVl,
        NROWS, DKV, D_MODEL, 3);
    // attention (emits bf16 hi/lo)
    attn_mma<<<dim3(QBLKS, 32, BATCH), 256, ATTN_SMEM>>>(
        pQh, pQl, pKh, pKl, pVh, pVl, mask, pact, pzro, paoh, paol);
    // split Wo, O projection -> fp32 out
    n = D_MODEL * D_MODEL / 4; split_bf16<<<(n + 255) / 256, 256>>>(Wo, pWoh, pWol, n);
    gemm_mma<<<dim3(D_MODEL / 128, NROWS / 128), 256, GEMM_SMEM_BYTES>>>(
        paoh, paol, pWoh, pWol, nullptr, nullptr, out, nullptr, nullptr, nullptr, nullptr,
        NROWS, D_MODEL, D_MODEL, 0);
}